// round 10
// baseline (speedup 1.0000x reference)
#include <cuda_runtime.h>
#include <cuda_fp16.h>
#include <cstdint>

// Problem constants
#define BB 8        // half-batch
#define NN 1024     // sequence length
#define EE 64       // embedding channels
#define CC 512      // CH
#define DD 4096     // BB * CC
#define EPS_LN 1e-5f

// ---------------- scratch (__device__ globals) ----------------------------
__device__ __half g_qTh[BB][CC][NN];      // A of scores: [c][n], k=n contig
__device__ __half g_kTh[DD][NN];          // B of scores: [d][n], k=n contig
__device__ __half g_vh[NN][DD];           // B of ctx:    [n][d], k=d contig
__device__ __half g_expS[BB][CC][DD];     // A of ctx: exp(LN(scores)), half
__device__ float  g_scores[BB][CC][DD];   // raw scores fp32 (for LN stats)
__device__ float  g_ctx[BB][CC][NN];      // fp32 [c][n]
__device__ float  g_sum[BB];
__device__ float  g_sumsq[BB];
__device__ float  g_rowinv[BB][CC];

// ---------------- helpers -------------------------------------------------
__device__ __forceinline__ void mma_f16(float c[4],
    uint32_t a0, uint32_t a1, uint32_t a2, uint32_t a3,
    uint32_t b0, uint32_t b1)
{
    asm volatile(
        "mma.sync.aligned.m16n8k16.row.col.f32.f16.f16.f32 "
        "{%0,%1,%2,%3},{%4,%5,%6,%7},{%8,%9},{%0,%1,%2,%3};"
        : "+f"(c[0]), "+f"(c[1]), "+f"(c[2]), "+f"(c[3])
        : "r"(a0), "r"(a1), "r"(a2), "r"(a3), "r"(b0), "r"(b1));
}

__device__ __forceinline__ void mma_tf32(float c[4],
    uint32_t a0, uint32_t a1, uint32_t a2, uint32_t a3,
    uint32_t b0, uint32_t b1)
{
    asm volatile(
        "mma.sync.aligned.m16n8k8.row.col.f32.tf32.tf32.f32 "
        "{%0,%1,%2,%3},{%4,%5,%6,%7},{%8,%9},{%0,%1,%2,%3};"
        : "+f"(c[0]), "+f"(c[1]), "+f"(c[2]), "+f"(c[3])
        : "r"(a0), "r"(a1), "r"(a2), "r"(a3), "r"(b0), "r"(b1));
}

#define LDSM4(d0, d1, d2, d3, addr) \
    asm volatile("ldmatrix.sync.aligned.m8n8.x4.shared.b16 {%0,%1,%2,%3}, [%4];" \
        : "=r"(d0), "=r"(d1), "=r"(d2), "=r"(d3) : "r"(addr))

__device__ __forceinline__ uint32_t tf32u(float x) {
    uint32_t u; asm("cvt.rna.tf32.f32 %0, %1;" : "=r"(u) : "f"(x)); return u;
}
__device__ __forceinline__ float tf32f(float x) { return __uint_as_float(tf32u(x)); }

__device__ __forceinline__ uint32_t smem_u32(const void* p) {
    uint32_t a;
    asm("{ .reg .u64 t; cvta.to.shared.u64 t, %1; cvt.u32.u64 %0, t; }" : "=r"(a) : "l"(p));
    return a;
}

// ---------------- kernel 1: q/k/v projections (round-9 verbatim) ----------
__global__ __launch_bounds__(256) void k_proj(
    const float* __restrict__ emb, const float* __restrict__ Wq,
    const float* __restrict__ Wk,  const float* __restrict__ Wv)
{
    __shared__ float embS[64][68];
    __shared__ float WS[64][68];
    __shared__ __half transS[64][72];

    int ntile = blockIdx.x, ctile = blockIdx.y, bz = blockIdx.z;
    int b = bz / 3, m = bz % 3;
    const float* W  = (m == 0) ? Wq : ((m == 1) ? Wk : Wv);
    const float* eb = emb + (size_t)((m == 0) ? (BB + b) : b) * NN * EE;
    int n0 = ntile * 64, c0 = ctile * 64;
    int t = threadIdx.x;

    if (ntile == 0 && ctile == 0 && bz == 0 && t < BB) {
        g_sum[t] = 0.f; g_sumsq[t] = 0.f;
    }

    #pragma unroll
    for (int r = 0; r < 4; r++) {
        int chunk = t + 256 * r;
        int row = chunk >> 4;
        int col = (chunk & 15) * 4;
        *(float4*)&embS[row][col] = *(const float4*)&eb[(size_t)(n0 + row) * EE + col];
        *(float4*)&WS[row][col]   = *(const float4*)&W[(size_t)(c0 + row) * EE + col];
    }
    __syncthreads();

    int ty = t >> 4, tx = t & 15;
    float acc[4][4] = {};
    #pragma unroll 16
    for (int e = 0; e < 64; e++) {
        float a[4], bv[4];
        #pragma unroll
        for (int i = 0; i < 4; i++) a[i]  = embS[ty + 16 * i][e];
        #pragma unroll
        for (int j = 0; j < 4; j++) bv[j] = WS[tx + 16 * j][e];
        #pragma unroll
        for (int i = 0; i < 4; i++)
            #pragma unroll
            for (int j = 0; j < 4; j++) acc[i][j] += a[i] * bv[j];
    }

    if (m == 2) {
        #pragma unroll
        for (int i = 0; i < 4; i++)
            #pragma unroll
            for (int j = 0; j < 4; j++)
                g_vh[n0 + ty + 16 * i][b * CC + c0 + tx + 16 * j] = __float2half_rn(acc[i][j]);
        return;
    }

    #pragma unroll
    for (int i = 0; i < 4; i++)
        #pragma unroll
        for (int j = 0; j < 4; j++)
            transS[tx + 16 * j][ty + 16 * i] = __float2half_rn(acc[i][j]);
    __syncthreads();

    int cl = t >> 2, g = t & 3;
    uint4 v0 = *(const uint4*)&transS[cl][g * 16];
    uint4 v1 = *(const uint4*)&transS[cl][g * 16 + 8];
    __half* dst = (m == 0) ? &g_qTh[b][c0 + cl][n0 + g * 16]
                           : &g_kTh[b * CC + c0 + cl][n0 + g * 16];
    *(uint4*)dst = v0;
    *(uint4*)(dst + 8) = v1;
}

// ---------------- kernel 2: scores GEMM (128x256 tile, ldmatrix) -----------
// S[b](512x4096) = qTh[b] @ kTh^T.  8 warps = 2m x 4n, 64x64 each.
// 48B smem rows (16 halfs + 8 pad): LDSM phase-conflict-free, 16B aligned.
__global__ __launch_bounds__(256, 1) void k_scores()
{
    __shared__ __align__(16) __half As[2][128 * 24];
    __shared__ __align__(16) __half Bs[2][256 * 24];
    __shared__ float red[256];

    const int m0 = blockIdx.x * 128, n0 = blockIdx.y * 256, b = blockIdx.z;
    const int t = threadIdx.x, lane = t & 31, warp = t >> 5;
    const int wm = (warp & 1) * 64, wn = (warp >> 1) * 64;

    const __half* A  = &g_qTh[b][m0][0];
    const __half* Bp = &g_kTh[n0][0];

    const int ar = t >> 1, ac = t & 1;      // A: 128 rows x 2 16B chunks
    uint4 fa, fb[2];
    auto ldg = [&](int k0) {
        fa = *(const uint4*)(A + (size_t)ar * NN + k0 + ac * 8);
        #pragma unroll
        for (int r = 0; r < 2; r++)
            fb[r] = *(const uint4*)(Bp + (size_t)(ar + 128 * r) * NN + k0 + ac * 8);
    };
    auto sts = [&](int buf) {
        *(uint4*)((char*)&As[buf][0] + ar * 48 + ac * 16) = fa;
        #pragma unroll
        for (int r = 0; r < 2; r++)
            *(uint4*)((char*)&Bs[buf][0] + (ar + 128 * r) * 48 + ac * 16) = fb[r];
    };

    // ldmatrix lane offsets (g = matrix index, r8 = row within matrix)
    const int g = lane >> 3, r8 = lane & 7;
    const uint32_t a_off = (uint32_t)((wm + ((g & 1) << 3) + r8) * 48 + ((g >> 1) << 4));
    const uint32_t b_off = (uint32_t)((wn + ((g >> 1) << 3) + r8) * 48 + ((g & 1) << 4));
    const uint32_t asu[2] = { smem_u32(&As[0][0]), smem_u32(&As[1][0]) };
    const uint32_t bsu[2] = { smem_u32(&Bs[0][0]), smem_u32(&Bs[1][0]) };

    float acc[4][8][4] = {};
    constexpr int T = NN / 16;
    ldg(0);

    for (int it = 0; it < T; it++) {
        int cur = it & 1;
        sts(cur);
        if (it + 1 < T) ldg((it + 1) * 16);
        __syncthreads();

        uint32_t aB = asu[cur], bB = bsu[cur];
        uint32_t af[4][4], bfr[4][4];
        #pragma unroll
        for (int mi = 0; mi < 4; mi++)
            LDSM4(af[mi][0], af[mi][1], af[mi][2], af[mi][3], aB + a_off + mi * (16 * 48));
        #pragma unroll
        for (int p = 0; p < 4; p++)
            LDSM4(bfr[p][0], bfr[p][1], bfr[p][2], bfr[p][3], bB + b_off + p * (16 * 48));
        #pragma unroll
        for (int mi = 0; mi < 4; mi++)
            #pragma unroll
            for (int ni = 0; ni < 8; ni++)
                mma_f16(acc[mi][ni], af[mi][0], af[mi][1], af[mi][2], af[mi][3],
                        bfr[ni >> 1][(ni & 1) * 2], bfr[ni >> 1][(ni & 1) * 2 + 1]);
    }

    float ls = 0.f, lq = 0.f;
    #pragma unroll
    for (int mi = 0; mi < 4; mi++)
        #pragma unroll
        for (int ni = 0; ni < 8; ni++)
            #pragma unroll
            for (int h = 0; h < 2; h++) {
                int row = m0 + wm + mi * 16 + (lane >> 2) + h * 8;
                int col = n0 + wn + ni * 8 + 2 * (lane & 3);
                float v0 = acc[mi][ni][2 * h + 0];
                float v1 = acc[mi][ni][2 * h + 1];
                float2 st; st.x = v0; st.y = v1;
                *(float2*)&g_scores[b][row][col] = st;
                ls += v0 + v1;
                lq += v0 * v0 + v1 * v1;
            }

    __syncthreads();
    red[t] = ls; __syncthreads();
    for (int s = 128; s > 0; s >>= 1) { if (t < s) red[t] += red[t + s]; __syncthreads(); }
    if (t == 0) atomicAdd(&g_sum[b], red[0]);
    __syncthreads();
    red[t] = lq; __syncthreads();
    for (int s = 128; s > 0; s >>= 1) { if (t < s) red[t] += red[t + s]; __syncthreads(); }
    if (t == 0) atomicAdd(&g_sumsq[b], red[0]);
}

// ---------------- kernel 3: LN + exp -> half + row-sum (round-9 verbatim) --
__global__ __launch_bounds__(256) void k_softmax()
{
    int c = blockIdx.x, b = blockIdx.y;
    int t = threadIdx.x;
    __shared__ float red[256];

    const float invCD = 1.0f / ((float)CC * (float)DD);
    float mean = g_sum[b] * invCD;
    float var  = g_sumsq[b] * invCD - mean * mean;
    float rstd = rsqrtf(var + EPS_LN);

    const float* row = &g_scores[b][c][0];
    __half* erow = &g_expS[b][c][0];
    float ls = 0.f;
    #pragma unroll
    for (int r = 0; r < 4; r++) {
        int idx = (t + 256 * r) * 4;
        float4 v = *(const float4*)&row[idx];
        v.x = __expf((v.x - mean) * rstd);
        v.y = __expf((v.y - mean) * rstd);
        v.z = __expf((v.z - mean) * rstd);
        v.w = __expf((v.w - mean) * rstd);
        ls += v.x + v.y + v.z + v.w;
        __half2 h0 = __floats2half2_rn(v.x, v.y);
        __half2 h1 = __floats2half2_rn(v.z, v.w);
        __half2* dst = (__half2*)&erow[idx];
        dst[0] = h0; dst[1] = h1;
    }
    red[t] = ls; __syncthreads();
    for (int s = 128; s > 0; s >>= 1) { if (t < s) red[t] += red[t + s]; __syncthreads(); }
    if (t == 0) g_rowinv[b][c] = 1.0f / red[0];
}

// ---------------- kernel 4: ctx GEMM (128x256 tile, ldmatrix) --------------
// ctx[b](512x1024) = expS[b] @ vh^T * rowinv.
__global__ __launch_bounds__(256, 1) void k_ctx()
{
    __shared__ __align__(16) __half As[2][128 * 24];
    __shared__ __align__(16) __half Bs[2][256 * 24];

    const int m0 = blockIdx.x * 128, n0 = blockIdx.y * 256, b = blockIdx.z;
    const int t = threadIdx.x, lane = t & 31, warp = t >> 5;
    const int wm = (warp & 1) * 64, wn = (warp >> 1) * 64;

    const __half* A  = &g_expS[b][m0][0];
    const __half* Bp = &g_vh[n0][0];

    const int ar = t >> 1, ac = t & 1;
    uint4 fa, fb[2];
    auto ldg = [&](int k0) {
        fa = *(const uint4*)(A + (size_t)ar * DD + k0 + ac * 8);
        #pragma unroll
        for (int r = 0; r < 2; r++)
            fb[r] = *(const uint4*)(Bp + (size_t)(ar + 128 * r) * DD + k0 + ac * 8);
    };
    auto sts = [&](int buf) {
        *(uint4*)((char*)&As[buf][0] + ar * 48 + ac * 16) = fa;
        #pragma unroll
        for (int r = 0; r < 2; r++)
            *(uint4*)((char*)&Bs[buf][0] + (ar + 128 * r) * 48 + ac * 16) = fb[r];
    };

    const int g = lane >> 3, r8 = lane & 7;
    const uint32_t a_off = (uint32_t)((wm + ((g & 1) << 3) + r8) * 48 + ((g >> 1) << 4));
    const uint32_t b_off = (uint32_t)((wn + ((g >> 1) << 3) + r8) * 48 + ((g & 1) << 4));
    const uint32_t asu[2] = { smem_u32(&As[0][0]), smem_u32(&As[1][0]) };
    const uint32_t bsu[2] = { smem_u32(&Bs[0][0]), smem_u32(&Bs[1][0]) };

    float acc[4][8][4] = {};
    constexpr int T = DD / 16;
    ldg(0);

    for (int it = 0; it < T; it++) {
        int cur = it & 1;
        sts(cur);
        if (it + 1 < T) ldg((it + 1) * 16);
        __syncthreads();

        uint32_t aB = asu[cur], bB = bsu[cur];
        uint32_t af[4][4], bfr[4][4];
        #pragma unroll
        for (int mi = 0; mi < 4; mi++)
            LDSM4(af[mi][0], af[mi][1], af[mi][2], af[mi][3], aB + a_off + mi * (16 * 48));
        #pragma unroll
        for (int p = 0; p < 4; p++)
            LDSM4(bfr[p][0], bfr[p][1], bfr[p][2], bfr[p][3], bB + b_off + p * (16 * 48));
        #pragma unroll
        for (int mi = 0; mi < 4; mi++)
            #pragma unroll
            for (int ni = 0; ni < 8; ni++)
                mma_f16(acc[mi][ni], af[mi][0], af[mi][1], af[mi][2], af[mi][3],
                        bfr[ni >> 1][(ni & 1) * 2], bfr[ni >> 1][(ni & 1) * 2 + 1]);
    }

    #pragma unroll
    for (int mi = 0; mi < 4; mi++)
        #pragma unroll
        for (int ni = 0; ni < 8; ni++)
            #pragma unroll
            for (int h = 0; h < 2; h++) {
                int row = m0 + wm + mi * 16 + (lane >> 2) + h * 8;
                int col = n0 + wn + ni * 8 + 2 * (lane & 3);
                float inv = g_rowinv[b][row];
                float2 st;
                st.x = acc[mi][ni][2 * h + 0] * inv;
                st.y = acc[mi][ni][2 * h + 1] * inv;
                *(float2*)&g_ctx[b][row][col] = st;
            }
}

// ---------------- kernel 5: output projection (tf32 mma, round-9 verbatim) -
__global__ __launch_bounds__(256) void k_out(
    const float* __restrict__ Wo, float* __restrict__ out)
{
    __shared__ float As[2][64 * 20];
    __shared__ float Bs[2][16 * 136];

    const int n0 = blockIdx.x * 128;
    const int b  = blockIdx.y;
    const int t = threadIdx.x, lane = t & 31, warp = t >> 5;
    const int wn = warp * 16;

    const int a_e = t >> 2,  a_k  = (t & 3) * 4;
    const int b_cc = t >> 5, b_nn = (t & 31) * 4;

    float4 fa, fb0, fb1;
    auto ldg = [&](int c0) {
        fa  = *(const float4*)&Wo[(size_t)a_e * CC + c0 + a_k];
        fb0 = *(const float4*)&g_ctx[b][c0 + b_cc][n0 + b_nn];
        fb1 = *(const float4*)&g_ctx[b][c0 + b_cc + 8][n0 + b_nn];
    };
    auto sts = [&](int buf) {
        float4 ca;
        ca.x = tf32f(fa.x); ca.y = tf32f(fa.y); ca.z = tf32f(fa.z); ca.w = tf32f(fa.w);
        *(float4*)&As[buf][a_e * 20 + a_k] = ca;
        float4 c0v, c1v;
        c0v.x = tf32f(fb0.x); c0v.y = tf32f(fb0.y); c0v.z = tf32f(fb0.z); c0v.w = tf32f(fb0.w);
        c1v.x = tf32f(fb1.x); c1v.y = tf32f(fb1.y); c1v.z = tf32f(fb1.z); c1v.w = tf32f(fb1.w);
        *(float4*)&Bs[buf][b_cc * 136 + b_nn] = c0v;
        *(float4*)&Bs[buf][(b_cc + 8) * 136 + b_nn] = c1v;
    };

    float acc[4][2][4] = {};
    constexpr int T = CC / 16;
    ldg(0);

    for (int it = 0; it < T; it++) {
        int cur = it & 1;
        sts(cur);
        if (it + 1 < T) ldg((it + 1) * 16);
        __syncthreads();

        const float* A_ = As[cur];
        const float* B_ = Bs[cur];
        #pragma unroll
        for (int ks = 0; ks < 16; ks += 8) {
            int kk = ks + (lane & 3);
            uint32_t af[4][4], bf[2][2];
            #pragma unroll
            for (int mi = 0; mi < 4; mi++) {
                int m = mi * 16 + (lane >> 2);
                af[mi][0] = __float_as_uint(A_[m * 20 + kk]);
                af[mi][1] = __float_as_uint(A_[(m + 8) * 20 + kk]);
                af[mi][2] = __float_as_uint(A_[m * 20 + kk + 4]);
                af[mi][3] = __float_as_uint(A_[(m + 8) * 20 + kk + 4]);
            }
            #pragma unroll
            for (int ni = 0; ni < 2; ni++) {
                int n = wn + ni * 8 + (lane >> 2);
                bf[ni][0] = __float_as_uint(B_[kk * 136 + n]);
                bf[ni][1] = __float_as_uint(B_[(kk + 4) * 136 + n]);
            }
            #pragma unroll
            for (int mi = 0; mi < 4; mi++)
                #pragma unroll
                for (int ni = 0; ni < 2; ni++)
                    mma_tf32(acc[mi][ni], af[mi][0], af[mi][1], af[mi][2], af[mi][3],
                             bf[ni][0], bf[ni][1]);
        }
    }

    #pragma unroll
    for (int mi = 0; mi < 4; mi++)
        #pragma unroll
        for (int ni = 0; ni < 2; ni++)
            #pragma unroll
            for (int h = 0; h < 2; h++) {
                int e = mi * 16 + (lane >> 2) + h * 8;
                int n = n0 + wn + ni * 8 + 2 * (lane & 3);
                out[((size_t)b * NN + n) * EE + e]       = acc[mi][ni][2 * h + 0];
                out[((size_t)b * NN + n + 1) * EE + e]   = acc[mi][ni][2 * h + 1];
            }
}

// ---------------- launch ---------------------------------------------------
extern "C" void kernel_launch(void* const* d_in, const int* in_sizes, int n_in,
                              void* d_out, int out_size)
{
    const float* emb = (const float*)d_in[0];
    const float* Wq  = (const float*)d_in[1];
    const float* Wk  = (const float*)d_in[2];
    const float* Wv  = (const float*)d_in[3];
    const float* Wo  = (const float*)d_in[4];
    float* out = (float*)d_out;

    dim3 g1(16, 8, 24);
    k_proj<<<g1, 256>>>(emb, Wq, Wk, Wv);

    dim3 g2(CC / 128, DD / 256, BB);     // 4 x 16 x 8
    k_scores<<<g2, 256>>>();

    dim3 g3(512, 8);
    k_softmax<<<g3, 256>>>();

    dim3 g4(CC / 128, NN / 256, BB);     // 4 x 4 x 8
    k_ctx<<<g4, 256>>>();

    dim3 g5(NN / 128, BB);               // 8 x 8
    k_out<<<g5, 256>>>(Wo, out);
}

// round 11
// speedup vs baseline: 1.1465x; 1.1465x over previous
#include <cuda_runtime.h>
#include <cuda_fp16.h>
#include <cstdint>

// Problem constants
#define BB 8        // half-batch
#define NN 1024     // sequence length
#define EE 64       // embedding channels
#define CC 512      // CH
#define DD 4096     // BB * CC
#define EPS_LN 1e-5f

// ---------------- scratch (__device__ globals) ----------------------------
__device__ __half g_qTh[BB][CC][NN];      // A of scores: [c][n], k=n contig
__device__ __half g_kTh[DD][NN];          // B of scores: [d][n], k=n contig
__device__ __half g_vh[NN][DD];           // B of ctx:    [n][d], k=d contig
__device__ __half g_sch[BB][CC][DD];      // scores fp16, then exp() in-place
__device__ float  g_ctx[BB][CC][NN];      // fp32 [c][n]
__device__ float  g_sum[BB];
__device__ float  g_sumsq[BB];
__device__ float  g_rowinv[BB][CC];

// ---------------- helpers -------------------------------------------------
__device__ __forceinline__ void mma_f16(float c[4],
    uint32_t a0, uint32_t a1, uint32_t a2, uint32_t a3,
    uint32_t b0, uint32_t b1)
{
    asm volatile(
        "mma.sync.aligned.m16n8k16.row.col.f32.f16.f16.f32 "
        "{%0,%1,%2,%3},{%4,%5,%6,%7},{%8,%9},{%0,%1,%2,%3};"
        : "+f"(c[0]), "+f"(c[1]), "+f"(c[2]), "+f"(c[3])
        : "r"(a0), "r"(a1), "r"(a2), "r"(a3), "r"(b0), "r"(b1));
}

__device__ __forceinline__ void mma_tf32(float c[4],
    uint32_t a0, uint32_t a1, uint32_t a2, uint32_t a3,
    uint32_t b0, uint32_t b1)
{
    asm volatile(
        "mma.sync.aligned.m16n8k8.row.col.f32.tf32.tf32.f32 "
        "{%0,%1,%2,%3},{%4,%5,%6,%7},{%8,%9},{%0,%1,%2,%3};"
        : "+f"(c[0]), "+f"(c[1]), "+f"(c[2]), "+f"(c[3])
        : "r"(a0), "r"(a1), "r"(a2), "r"(a3), "r"(b0), "r"(b1));
}

#define LDSM4(d0, d1, d2, d3, addr) \
    asm volatile("ldmatrix.sync.aligned.m8n8.x4.shared.b16 {%0,%1,%2,%3}, [%4];" \
        : "=r"(d0), "=r"(d1), "=r"(d2), "=r"(d3) : "r"(addr))

__device__ __forceinline__ uint32_t tf32u(float x) {
    uint32_t u; asm("cvt.rna.tf32.f32 %0, %1;" : "=r"(u) : "f"(x)); return u;
}
__device__ __forceinline__ float tf32f(float x) { return __uint_as_float(tf32u(x)); }

__device__ __forceinline__ uint32_t smem_u32(const void* p) {
    uint32_t a;
    asm("{ .reg .u64 t; cvta.to.shared.u64 t, %1; cvt.u32.u64 %0, t; }" : "=r"(a) : "l"(p));
    return a;
}

// ---------------- kernel 1: q/k/v projections (round-9 verbatim) ----------
__global__ __launch_bounds__(256) void k_proj(
    const float* __restrict__ emb, const float* __restrict__ Wq,
    const float* __restrict__ Wk,  const float* __restrict__ Wv)
{
    __shared__ float embS[64][68];
    __shared__ float WS[64][68];
    __shared__ __half transS[64][72];

    int ntile = blockIdx.x, ctile = blockIdx.y, bz = blockIdx.z;
    int b = bz / 3, m = bz % 3;
    const float* W  = (m == 0) ? Wq : ((m == 1) ? Wk : Wv);
    const float* eb = emb + (size_t)((m == 0) ? (BB + b) : b) * NN * EE;
    int n0 = ntile * 64, c0 = ctile * 64;
    int t = threadIdx.x;

    if (ntile == 0 && ctile == 0 && bz == 0 && t < BB) {
        g_sum[t] = 0.f; g_sumsq[t] = 0.f;
    }

    #pragma unroll
    for (int r = 0; r < 4; r++) {
        int chunk = t + 256 * r;
        int row = chunk >> 4;
        int col = (chunk & 15) * 4;
        *(float4*)&embS[row][col] = *(const float4*)&eb[(size_t)(n0 + row) * EE + col];
        *(float4*)&WS[row][col]   = *(const float4*)&W[(size_t)(c0 + row) * EE + col];
    }
    __syncthreads();

    int ty = t >> 4, tx = t & 15;
    float acc[4][4] = {};
    #pragma unroll 16
    for (int e = 0; e < 64; e++) {
        float a[4], bv[4];
        #pragma unroll
        for (int i = 0; i < 4; i++) a[i]  = embS[ty + 16 * i][e];
        #pragma unroll
        for (int j = 0; j < 4; j++) bv[j] = WS[tx + 16 * j][e];
        #pragma unroll
        for (int i = 0; i < 4; i++)
            #pragma unroll
            for (int j = 0; j < 4; j++) acc[i][j] += a[i] * bv[j];
    }

    if (m == 2) {
        #pragma unroll
        for (int i = 0; i < 4; i++)
            #pragma unroll
            for (int j = 0; j < 4; j++)
                g_vh[n0 + ty + 16 * i][b * CC + c0 + tx + 16 * j] = __float2half_rn(acc[i][j]);
        return;
    }

    #pragma unroll
    for (int i = 0; i < 4; i++)
        #pragma unroll
        for (int j = 0; j < 4; j++)
            transS[tx + 16 * j][ty + 16 * i] = __float2half_rn(acc[i][j]);
    __syncthreads();

    int cl = t >> 2, g = t & 3;
    uint4 v0 = *(const uint4*)&transS[cl][g * 16];
    uint4 v1 = *(const uint4*)&transS[cl][g * 16 + 8];
    __half* dst = (m == 0) ? &g_qTh[b][c0 + cl][n0 + g * 16]
                           : &g_kTh[b * CC + c0 + cl][n0 + g * 16];
    *(uint4*)dst = v0;
    *(uint4*)(dst + 8) = v1;
}

// ---------------- kernel 2: scores GEMM ------------------------------------
// 128x128 block, 128 threads, 4 warps of 64x64 (2 CTAs/SM -> desynced overlap)
// KTILE=32, 80B smem rows (round-8 proven), ldmatrix fragment loads.
__global__ __launch_bounds__(128, 2) void k_scores()
{
    __shared__ __align__(16) __half As[2][128 * 40];
    __shared__ __align__(16) __half Bs[2][128 * 40];
    __shared__ float red[128];

    const int m0 = blockIdx.x * 128, n0 = blockIdx.y * 128, b = blockIdx.z;
    const int t = threadIdx.x, lane = t & 31, warp = t >> 5;
    const int wm = (warp & 1) * 64, wn = (warp >> 1) * 64;

    const __half* A  = &g_qTh[b][m0][0];
    const __half* Bp = &g_kTh[n0][0];

    const int srow = t >> 2;    // 0..31, +32 per rep
    const int sc   = t & 3;     // 16B chunk within 64B of payload

    uint4 fa[4], fb[4];
    auto ldg = [&](int k0) {
        #pragma unroll
        for (int r = 0; r < 4; r++) {
            int row = srow + 32 * r;
            fa[r] = *(const uint4*)(A  + (size_t)row * NN + k0 + sc * 8);
            fb[r] = *(const uint4*)(Bp + (size_t)row * NN + k0 + sc * 8);
        }
    };
    auto sts = [&](int buf) {
        #pragma unroll
        for (int r = 0; r < 4; r++) {
            int row = srow + 32 * r;
            *(uint4*)((char*)&As[buf][0] + row * 80 + sc * 16) = fa[r];
            *(uint4*)((char*)&Bs[buf][0] + row * 80 + sc * 16) = fb[r];
        }
    };

    // ldmatrix lane offsets (g = matrix index, r8 = row within matrix)
    const int g = lane >> 3, r8 = lane & 7;
    const uint32_t a_off = (uint32_t)((wm + ((g & 1) << 3) + r8) * 80 + ((g >> 1) << 4));
    const uint32_t b_off = (uint32_t)((wn + ((g >> 1) << 3) + r8) * 80 + ((g & 1) << 4));
    const uint32_t asu[2] = { smem_u32(&As[0][0]), smem_u32(&As[1][0]) };
    const uint32_t bsu[2] = { smem_u32(&Bs[0][0]), smem_u32(&Bs[1][0]) };

    float acc[4][8][4] = {};
    constexpr int T = NN / 32;
    ldg(0);

    for (int it = 0; it < T; it++) {
        int cur = it & 1;
        sts(cur);
        if (it + 1 < T) ldg((it + 1) * 32);
        __syncthreads();

        #pragma unroll
        for (int ks = 0; ks < 2; ks++) {
            uint32_t aB = asu[cur] + ks * 32, bB = bsu[cur] + ks * 32;
            uint32_t af[4][4], bfr[4][4];
            #pragma unroll
            for (int mi = 0; mi < 4; mi++)
                LDSM4(af[mi][0], af[mi][1], af[mi][2], af[mi][3], aB + a_off + mi * (16 * 80));
            #pragma unroll
            for (int p = 0; p < 4; p++)
                LDSM4(bfr[p][0], bfr[p][1], bfr[p][2], bfr[p][3], bB + b_off + p * (16 * 80));
            #pragma unroll
            for (int mi = 0; mi < 4; mi++)
                #pragma unroll
                for (int ni = 0; ni < 8; ni++)
                    mma_f16(acc[mi][ni], af[mi][0], af[mi][1], af[mi][2], af[mi][3],
                            bfr[ni >> 1][(ni & 1) * 2], bfr[ni >> 1][(ni & 1) * 2 + 1]);
        }
    }

    // epilogue: fp16 scores (stats from fp32 accumulators pre-rounding)
    float ls = 0.f, lq = 0.f;
    #pragma unroll
    for (int mi = 0; mi < 4; mi++)
        #pragma unroll
        for (int ni = 0; ni < 8; ni++)
            #pragma unroll
            for (int h = 0; h < 2; h++) {
                int row = m0 + wm + mi * 16 + (lane >> 2) + h * 8;
                int col = n0 + wn + ni * 8 + 2 * (lane & 3);
                float v0 = acc[mi][ni][2 * h + 0];
                float v1 = acc[mi][ni][2 * h + 1];
                *(__half2*)&g_sch[b][row][col] = __floats2half2_rn(v0, v1);
                ls += v0 + v1;
                lq += v0 * v0 + v1 * v1;
            }

    __syncthreads();
    red[t] = ls; __syncthreads();
    for (int s = 64; s > 0; s >>= 1) { if (t < s) red[t] += red[t + s]; __syncthreads(); }
    if (t == 0) atomicAdd(&g_sum[b], red[0]);
    __syncthreads();
    red[t] = lq; __syncthreads();
    for (int s = 64; s > 0; s >>= 1) { if (t < s) red[t] += red[t + s]; __syncthreads(); }
    if (t == 0) atomicAdd(&g_sumsq[b], red[0]);
}

// ---------------- kernel 3: LN + exp (in-place, half) + row-sum -----------
__global__ __launch_bounds__(256) void k_softmax()
{
    int c = blockIdx.x, b = blockIdx.y;
    int t = threadIdx.x;
    __shared__ float red[256];

    const float invCD = 1.0f / ((float)CC * (float)DD);
    float mean = g_sum[b] * invCD;
    float var  = g_sumsq[b] * invCD - mean * mean;
    float rstd = rsqrtf(var + EPS_LN);

    __half* row = &g_sch[b][c][0];
    float ls = 0.f;
    #pragma unroll
    for (int r = 0; r < 2; r++) {
        int idx = (t + 256 * r) * 8;
        uint4 v = *(const uint4*)&row[idx];
        __half2* hp = (__half2*)&v;
        #pragma unroll
        for (int j = 0; j < 4; j++) {
            float2 f = __half22float2(hp[j]);
            f.x = __expf((f.x - mean) * rstd);
            f.y = __expf((f.y - mean) * rstd);
            ls += f.x + f.y;
            hp[j] = __floats2half2_rn(f.x, f.y);
        }
        *(uint4*)&row[idx] = v;
    }
    red[t] = ls; __syncthreads();
    for (int s = 128; s > 0; s >>= 1) { if (t < s) red[t] += red[t + s]; __syncthreads(); }
    if (t == 0) g_rowinv[b][c] = 1.0f / red[0];
}

// ---------------- kernel 4: ctx GEMM ---------------------------------------
// Same structure as k_scores; A = exp(scores) half, B = vh, K = DD.
__global__ __launch_bounds__(128, 2) void k_ctx()
{
    __shared__ __align__(16) __half As[2][128 * 40];
    __shared__ __align__(16) __half Bs[2][128 * 40];

    const int m0 = blockIdx.x * 128, n0 = blockIdx.y * 128, b = blockIdx.z;
    const int t = threadIdx.x, lane = t & 31, warp = t >> 5;
    const int wm = (warp & 1) * 64, wn = (warp >> 1) * 64;

    const __half* A  = &g_sch[b][m0][0];
    const __half* Bp = &g_vh[n0][0];

    const int srow = t >> 2;
    const int sc   = t & 3;

    uint4 fa[4], fb[4];
    auto ldg = [&](int k0) {
        #pragma unroll
        for (int r = 0; r < 4; r++) {
            int row = srow + 32 * r;
            fa[r] = *(const uint4*)(A  + (size_t)row * DD + k0 + sc * 8);
            fb[r] = *(const uint4*)(Bp + (size_t)row * DD + k0 + sc * 8);
        }
    };
    auto sts = [&](int buf) {
        #pragma unroll
        for (int r = 0; r < 4; r++) {
            int row = srow + 32 * r;
            *(uint4*)((char*)&As[buf][0] + row * 80 + sc * 16) = fa[r];
            *(uint4*)((char*)&Bs[buf][0] + row * 80 + sc * 16) = fb[r];
        }
    };

    const int g = lane >> 3, r8 = lane & 7;
    const uint32_t a_off = (uint32_t)((wm + ((g & 1) << 3) + r8) * 80 + ((g >> 1) << 4));
    const uint32_t b_off = (uint32_t)((wn + ((g >> 1) << 3) + r8) * 80 + ((g & 1) << 4));
    const uint32_t asu[2] = { smem_u32(&As[0][0]), smem_u32(&As[1][0]) };
    const uint32_t bsu[2] = { smem_u32(&Bs[0][0]), smem_u32(&Bs[1][0]) };

    float acc[4][8][4] = {};
    constexpr int T = DD / 32;
    ldg(0);

    for (int it = 0; it < T; it++) {
        int cur = it & 1;
        sts(cur);
        if (it + 1 < T) ldg((it + 1) * 32);
        __syncthreads();

        #pragma unroll
        for (int ks = 0; ks < 2; ks++) {
            uint32_t aB = asu[cur] + ks * 32, bB = bsu[cur] + ks * 32;
            uint32_t af[4][4], bfr[4][4];
            #pragma unroll
            for (int mi = 0; mi < 4; mi++)
                LDSM4(af[mi][0], af[mi][1], af[mi][2], af[mi][3], aB + a_off + mi * (16 * 80));
            #pragma unroll
            for (int p = 0; p < 4; p++)
                LDSM4(bfr[p][0], bfr[p][1], bfr[p][2], bfr[p][3], bB + b_off + p * (16 * 80));
            #pragma unroll
            for (int mi = 0; mi < 4; mi++)
                #pragma unroll
                for (int ni = 0; ni < 8; ni++)
                    mma_f16(acc[mi][ni], af[mi][0], af[mi][1], af[mi][2], af[mi][3],
                            bfr[ni >> 1][(ni & 1) * 2], bfr[ni >> 1][(ni & 1) * 2 + 1]);
        }
    }

    #pragma unroll
    for (int mi = 0; mi < 4; mi++)
        #pragma unroll
        for (int ni = 0; ni < 8; ni++)
            #pragma unroll
            for (int h = 0; h < 2; h++) {
                int row = m0 + wm + mi * 16 + (lane >> 2) + h * 8;
                int col = n0 + wn + ni * 8 + 2 * (lane & 3);
                float inv = g_rowinv[b][row];
                float2 st;
                st.x = acc[mi][ni][2 * h + 0] * inv;
                st.y = acc[mi][ni][2 * h + 1] * inv;
                *(float2*)&g_ctx[b][row][col] = st;
            }
}

// ---------------- kernel 5: output projection (tf32 mma, round-9 verbatim) -
__global__ __launch_bounds__(256) void k_out(
    const float* __restrict__ Wo, float* __restrict__ out)
{
    __shared__ float As[2][64 * 20];
    __shared__ float Bs[2][16 * 136];

    const int n0 = blockIdx.x * 128;
    const int b  = blockIdx.y;
    const int t = threadIdx.x, lane = t & 31, warp = t >> 5;
    const int wn = warp * 16;

    const int a_e = t >> 2,  a_k  = (t & 3) * 4;
    const int b_cc = t >> 5, b_nn = (t & 31) * 4;

    float4 fa, fb0, fb1;
    auto ldg = [&](int c0) {
        fa  = *(const float4*)&Wo[(size_t)a_e * CC + c0 + a_k];
        fb0 = *(const float4*)&g_ctx[b][c0 + b_cc][n0 + b_nn];
        fb1 = *(const float4*)&g_ctx[b][c0 + b_cc + 8][n0 + b_nn];
    };
    auto sts = [&](int buf) {
        float4 ca;
        ca.x = tf32f(fa.x); ca.y = tf32f(fa.y); ca.z = tf32f(fa.z); ca.w = tf32f(fa.w);
        *(float4*)&As[buf][a_e * 20 + a_k] = ca;
        float4 c0v, c1v;
        c0v.x = tf32f(fb0.x); c0v.y = tf32f(fb0.y); c0v.z = tf32f(fb0.z); c0v.w = tf32f(fb0.w);
        c1v.x = tf32f(fb1.x); c1v.y = tf32f(fb1.y); c1v.z = tf32f(fb1.z); c1v.w = tf32f(fb1.w);
        *(float4*)&Bs[buf][b_cc * 136 + b_nn] = c0v;
        *(float4*)&Bs[buf][(b_cc + 8) * 136 + b_nn] = c1v;
    };

    float acc[4][2][4] = {};
    constexpr int T = CC / 16;
    ldg(0);

    for (int it = 0; it < T; it++) {
        int cur = it & 1;
        sts(cur);
        if (it + 1 < T) ldg((it + 1) * 16);
        __syncthreads();

        const float* A_ = As[cur];
        const float* B_ = Bs[cur];
        #pragma unroll
        for (int ks = 0; ks < 16; ks += 8) {
            int kk = ks + (lane & 3);
            uint32_t af[4][4], bf[2][2];
            #pragma unroll
            for (int mi = 0; mi < 4; mi++) {
                int m = mi * 16 + (lane >> 2);
                af[mi][0] = __float_as_uint(A_[m * 20 + kk]);
                af[mi][1] = __float_as_uint(A_[(m + 8) * 20 + kk]);
                af[mi][2] = __float_as_uint(A_[m * 20 + kk + 4]);
                af[mi][3] = __float_as_uint(A_[(m + 8) * 20 + kk + 4]);
            }
            #pragma unroll
            for (int ni = 0; ni < 2; ni++) {
                int n = wn + ni * 8 + (lane >> 2);
                bf[ni][0] = __float_as_uint(B_[kk * 136 + n]);
                bf[ni][1] = __float_as_uint(B_[(kk + 4) * 136 + n]);
            }
            #pragma unroll
            for (int mi = 0; mi < 4; mi++)
                #pragma unroll
                for (int ni = 0; ni < 2; ni++)
                    mma_tf32(acc[mi][ni], af[mi][0], af[mi][1], af[mi][2], af[mi][3],
                             bf[ni][0], bf[ni][1]);
        }
    }

    #pragma unroll
    for (int mi = 0; mi < 4; mi++)
        #pragma unroll
        for (int ni = 0; ni < 2; ni++)
            #pragma unroll
            for (int h = 0; h < 2; h++) {
                int e = mi * 16 + (lane >> 2) + h * 8;
                int n = n0 + wn + ni * 8 + 2 * (lane & 3);
                out[((size_t)b * NN + n) * EE + e]       = acc[mi][ni][2 * h + 0];
                out[((size_t)b * NN + n + 1) * EE + e]   = acc[mi][ni][2 * h + 1];
            }
}

// ---------------- launch ---------------------------------------------------
extern "C" void kernel_launch(void* const* d_in, const int* in_sizes, int n_in,
                              void* d_out, int out_size)
{
    const float* emb = (const float*)d_in[0];
    const float* Wq  = (const float*)d_in[1];
    const float* Wk  = (const float*)d_in[2];
    const float* Wv  = (const float*)d_in[3];
    const float* Wo  = (const float*)d_in[4];
    float* out = (float*)d_out;

    dim3 g1(16, 8, 24);
    k_proj<<<g1, 256>>>(emb, Wq, Wk, Wv);

    dim3 g2(CC / 128, DD / 128, BB);     // 4 x 32 x 8 = 1024 blocks
    k_scores<<<g2, 128>>>();

    dim3 g3(512, 8);
    k_softmax<<<g3, 256>>>();

    dim3 g4(CC / 128, NN / 128, BB);     // 4 x 8 x 8 = 256 blocks
    k_ctx<<<g4, 128>>>();

    dim3 g5(NN / 128, BB);               // 8 x 8
    k_out<<<g5, 256>>>(Wo, out);
}

// round 12
// speedup vs baseline: 1.1490x; 1.0021x over previous
#include <cuda_runtime.h>
#include <cuda_fp16.h>
#include <cstdint>

// Problem constants
#define BB 8        // half-batch
#define NN 1024     // sequence length
#define EE 64       // embedding channels
#define CC 512      // CH
#define DD 4096     // BB * CC
#define EPS_LN 1e-5f

// ---------------- scratch (__device__ globals) ----------------------------
__device__ __half g_qTh[BB][CC][NN];      // A of scores: [c][n], k=n contig
__device__ __half g_kTh[DD][NN];          // B of scores: [d][n], k=n contig
__device__ __half g_vh[NN][DD];           // B of ctx:    [n][d], k=d contig
__device__ __half g_sch[BB][CC][DD];      // scores fp16, then exp() in-place
__device__ float  g_ctx[BB][CC][NN];      // fp32 [c][n]
__device__ float  g_sum[BB];
__device__ float  g_sumsq[BB];
__device__ float  g_rowinv[BB][CC];

// ---------------- helpers -------------------------------------------------
__device__ __forceinline__ void mma_f16(float c[4],
    uint32_t a0, uint32_t a1, uint32_t a2, uint32_t a3,
    uint32_t b0, uint32_t b1)
{
    asm volatile(
        "mma.sync.aligned.m16n8k16.row.col.f32.f16.f16.f32 "
        "{%0,%1,%2,%3},{%4,%5,%6,%7},{%8,%9},{%0,%1,%2,%3};"
        : "+f"(c[0]), "+f"(c[1]), "+f"(c[2]), "+f"(c[3])
        : "r"(a0), "r"(a1), "r"(a2), "r"(a3), "r"(b0), "r"(b1));
}

__device__ __forceinline__ void mma_tf32(float c[4],
    uint32_t a0, uint32_t a1, uint32_t a2, uint32_t a3,
    uint32_t b0, uint32_t b1)
{
    asm volatile(
        "mma.sync.aligned.m16n8k8.row.col.f32.tf32.tf32.f32 "
        "{%0,%1,%2,%3},{%4,%5,%6,%7},{%8,%9},{%0,%1,%2,%3};"
        : "+f"(c[0]), "+f"(c[1]), "+f"(c[2]), "+f"(c[3])
        : "r"(a0), "r"(a1), "r"(a2), "r"(a3), "r"(b0), "r"(b1));
}

#define LDSM4(d0, d1, d2, d3, addr) \
    asm volatile("ldmatrix.sync.aligned.m8n8.x4.shared.b16 {%0,%1,%2,%3}, [%4];" \
        : "=r"(d0), "=r"(d1), "=r"(d2), "=r"(d3) : "r"(addr))

__device__ __forceinline__ uint32_t tf32u(float x) {
    uint32_t u; asm("cvt.rna.tf32.f32 %0, %1;" : "=r"(u) : "f"(x)); return u;
}
__device__ __forceinline__ float tf32f(float x) { return __uint_as_float(tf32u(x)); }

__device__ __forceinline__ uint32_t smem_u32(const void* p) {
    uint32_t a;
    asm("{ .reg .u64 t; cvta.to.shared.u64 t, %1; cvt.u32.u64 %0, t; }" : "=r"(a) : "l"(p));
    return a;
}

// ---------------- kernel 1: q/k/v projections (round-9 verbatim) ----------
__global__ __launch_bounds__(256) void k_proj(
    const float* __restrict__ emb, const float* __restrict__ Wq,
    const float* __restrict__ Wk,  const float* __restrict__ Wv)
{
    __shared__ float embS[64][68];
    __shared__ float WS[64][68];
    __shared__ __half transS[64][72];

    int ntile = blockIdx.x, ctile = blockIdx.y, bz = blockIdx.z;
    int b = bz / 3, m = bz % 3;
    const float* W  = (m == 0) ? Wq : ((m == 1) ? Wk : Wv);
    const float* eb = emb + (size_t)((m == 0) ? (BB + b) : b) * NN * EE;
    int n0 = ntile * 64, c0 = ctile * 64;
    int t = threadIdx.x;

    if (ntile == 0 && ctile == 0 && bz == 0 && t < BB) {
        g_sum[t] = 0.f; g_sumsq[t] = 0.f;
    }

    #pragma unroll
    for (int r = 0; r < 4; r++) {
        int chunk = t + 256 * r;
        int row = chunk >> 4;
        int col = (chunk & 15) * 4;
        *(float4*)&embS[row][col] = *(const float4*)&eb[(size_t)(n0 + row) * EE + col];
        *(float4*)&WS[row][col]   = *(const float4*)&W[(size_t)(c0 + row) * EE + col];
    }
    __syncthreads();

    int ty = t >> 4, tx = t & 15;
    float acc[4][4] = {};
    #pragma unroll 16
    for (int e = 0; e < 64; e++) {
        float a[4], bv[4];
        #pragma unroll
        for (int i = 0; i < 4; i++) a[i]  = embS[ty + 16 * i][e];
        #pragma unroll
        for (int j = 0; j < 4; j++) bv[j] = WS[tx + 16 * j][e];
        #pragma unroll
        for (int i = 0; i < 4; i++)
            #pragma unroll
            for (int j = 0; j < 4; j++) acc[i][j] += a[i] * bv[j];
    }

    if (m == 2) {
        #pragma unroll
        for (int i = 0; i < 4; i++)
            #pragma unroll
            for (int j = 0; j < 4; j++)
                g_vh[n0 + ty + 16 * i][b * CC + c0 + tx + 16 * j] = __float2half_rn(acc[i][j]);
        return;
    }

    #pragma unroll
    for (int i = 0; i < 4; i++)
        #pragma unroll
        for (int j = 0; j < 4; j++)
            transS[tx + 16 * j][ty + 16 * i] = __float2half_rn(acc[i][j]);
    __syncthreads();

    int cl = t >> 2, g = t & 3;
    uint4 v0 = *(const uint4*)&transS[cl][g * 16];
    uint4 v1 = *(const uint4*)&transS[cl][g * 16 + 8];
    __half* dst = (m == 0) ? &g_qTh[b][c0 + cl][n0 + g * 16]
                           : &g_kTh[b * CC + c0 + cl][n0 + g * 16];
    *(uint4*)dst = v0;
    *(uint4*)(dst + 8) = v1;
}

// ---------------- kernel 2: scores GEMM (round-11 mainloop) ----------------
__global__ __launch_bounds__(128, 2) void k_scores()
{
    __shared__ __align__(16) __half As[2][128 * 40];
    __shared__ __align__(16) __half Bs[2][128 * 40];

    const int m0 = blockIdx.x * 128, n0 = blockIdx.y * 128, b = blockIdx.z;
    const int t = threadIdx.x, lane = t & 31, warp = t >> 5;
    const int wm = (warp & 1) * 64, wn = (warp >> 1) * 64;

    const __half* A  = &g_qTh[b][m0][0];
    const __half* Bp = &g_kTh[n0][0];

    const int srow = t >> 2;    // 0..31, +32 per rep
    const int sc   = t & 3;     // 16B chunk

    uint4 fa[4], fb[4];
    auto ldg = [&](int k0) {
        #pragma unroll
        for (int r = 0; r < 4; r++) {
            int row = srow + 32 * r;
            fa[r] = *(const uint4*)(A  + (size_t)row * NN + k0 + sc * 8);
            fb[r] = *(const uint4*)(Bp + (size_t)row * NN + k0 + sc * 8);
        }
    };
    auto sts = [&](int buf) {
        #pragma unroll
        for (int r = 0; r < 4; r++) {
            int row = srow + 32 * r;
            *(uint4*)((char*)&As[buf][0] + row * 80 + sc * 16) = fa[r];
            *(uint4*)((char*)&Bs[buf][0] + row * 80 + sc * 16) = fb[r];
        }
    };

    const int g = lane >> 3, r8 = lane & 7;
    const uint32_t a_off = (uint32_t)((wm + ((g & 1) << 3) + r8) * 80 + ((g >> 1) << 4));
    const uint32_t b_off = (uint32_t)((wn + ((g >> 1) << 3) + r8) * 80 + ((g & 1) << 4));
    const uint32_t asu[2] = { smem_u32(&As[0][0]), smem_u32(&As[1][0]) };
    const uint32_t bsu[2] = { smem_u32(&Bs[0][0]), smem_u32(&Bs[1][0]) };

    float acc[4][8][4] = {};
    constexpr int T = NN / 32;
    ldg(0);

    for (int it = 0; it < T; it++) {
        int cur = it & 1;
        sts(cur);
        if (it + 1 < T) ldg((it + 1) * 32);
        __syncthreads();

        #pragma unroll
        for (int ks = 0; ks < 2; ks++) {
            uint32_t aB = asu[cur] + ks * 32, bB = bsu[cur] + ks * 32;
            uint32_t af[4][4], bfr[4][4];
            #pragma unroll
            for (int mi = 0; mi < 4; mi++)
                LDSM4(af[mi][0], af[mi][1], af[mi][2], af[mi][3], aB + a_off + mi * (16 * 80));
            #pragma unroll
            for (int p = 0; p < 4; p++)
                LDSM4(bfr[p][0], bfr[p][1], bfr[p][2], bfr[p][3], bB + b_off + p * (16 * 80));
            #pragma unroll
            for (int mi = 0; mi < 4; mi++)
                #pragma unroll
                for (int ni = 0; ni < 8; ni++)
                    mma_f16(acc[mi][ni], af[mi][0], af[mi][1], af[mi][2], af[mi][3],
                            bfr[ni >> 1][(ni & 1) * 2], bfr[ni >> 1][(ni & 1) * 2 + 1]);
        }
    }

    // epilogue: fp16 scores; stats via warp shuffle + 1 atomic per warp
    float ls = 0.f, lq = 0.f;
    #pragma unroll
    for (int mi = 0; mi < 4; mi++)
        #pragma unroll
        for (int ni = 0; ni < 8; ni++)
            #pragma unroll
            for (int h = 0; h < 2; h++) {
                int row = m0 + wm + mi * 16 + (lane >> 2) + h * 8;
                int col = n0 + wn + ni * 8 + 2 * (lane & 3);
                float v0 = acc[mi][ni][2 * h + 0];
                float v1 = acc[mi][ni][2 * h + 1];
                *(__half2*)&g_sch[b][row][col] = __floats2half2_rn(v0, v1);
                ls += v0 + v1;
                lq += v0 * v0 + v1 * v1;
            }

    #pragma unroll
    for (int o = 16; o > 0; o >>= 1) {
        ls += __shfl_xor_sync(0xffffffffu, ls, o);
        lq += __shfl_xor_sync(0xffffffffu, lq, o);
    }
    if (lane == 0) {
        atomicAdd(&g_sum[b], ls);
        atomicAdd(&g_sumsq[b], lq);
    }
}

// ---------------- kernel 3: LN + exp (in-place, half) + row-sum -----------
__global__ __launch_bounds__(128) void k_softmax()
{
    int c = blockIdx.x, b = blockIdx.y;
    int t = threadIdx.x, lane = t & 31, warp = t >> 5;
    __shared__ float red[4];

    const float invCD = 1.0f / ((float)CC * (float)DD);
    float mean = g_sum[b] * invCD;
    float var  = g_sumsq[b] * invCD - mean * mean;
    float rstd = rsqrtf(var + EPS_LN);

    __half* row = &g_sch[b][c][0];
    float ls = 0.f;
    #pragma unroll
    for (int r = 0; r < 4; r++) {
        int idx = (t + 128 * r) * 8;
        uint4 v = *(const uint4*)&row[idx];
        __half2* hp = (__half2*)&v;
        #pragma unroll
        for (int j = 0; j < 4; j++) {
            float2 f = __half22float2(hp[j]);
            f.x = __expf((f.x - mean) * rstd);
            f.y = __expf((f.y - mean) * rstd);
            ls += f.x + f.y;
            hp[j] = __floats2half2_rn(f.x, f.y);
        }
        *(uint4*)&row[idx] = v;
    }
    #pragma unroll
    for (int o = 16; o > 0; o >>= 1) ls += __shfl_xor_sync(0xffffffffu, ls, o);
    if (lane == 0) red[warp] = ls;
    __syncthreads();
    if (t == 0) g_rowinv[b][c] = 1.0f / (red[0] + red[1] + red[2] + red[3]);
}

// ---------------- kernel 4: ctx GEMM (round-11 verbatim) -------------------
__global__ __launch_bounds__(128, 2) void k_ctx()
{
    __shared__ __align__(16) __half As[2][128 * 40];
    __shared__ __align__(16) __half Bs[2][128 * 40];

    const int m0 = blockIdx.x * 128, n0 = blockIdx.y * 128, b = blockIdx.z;
    const int t = threadIdx.x, lane = t & 31, warp = t >> 5;
    const int wm = (warp & 1) * 64, wn = (warp >> 1) * 64;

    const __half* A  = &g_sch[b][m0][0];
    const __half* Bp = &g_vh[n0][0];

    const int srow = t >> 2;
    const int sc   = t & 3;

    uint4 fa[4], fb[4];
    auto ldg = [&](int k0) {
        #pragma unroll
        for (int r = 0; r < 4; r++) {
            int row = srow + 32 * r;
            fa[r] = *(const uint4*)(A  + (size_t)row * DD + k0 + sc * 8);
            fb[r] = *(const uint4*)(Bp + (size_t)row * DD + k0 + sc * 8);
        }
    };
    auto sts = [&](int buf) {
        #pragma unroll
        for (int r = 0; r < 4; r++) {
            int row = srow + 32 * r;
            *(uint4*)((char*)&As[buf][0] + row * 80 + sc * 16) = fa[r];
            *(uint4*)((char*)&Bs[buf][0] + row * 80 + sc * 16) = fb[r];
        }
    };

    const int g = lane >> 3, r8 = lane & 7;
    const uint32_t a_off = (uint32_t)((wm + ((g & 1) << 3) + r8) * 80 + ((g >> 1) << 4));
    const uint32_t b_off = (uint32_t)((wn + ((g >> 1) << 3) + r8) * 80 + ((g & 1) << 4));
    const uint32_t asu[2] = { smem_u32(&As[0][0]), smem_u32(&As[1][0]) };
    const uint32_t bsu[2] = { smem_u32(&Bs[0][0]), smem_u32(&Bs[1][0]) };

    float acc[4][8][4] = {};
    constexpr int T = DD / 32;
    ldg(0);

    for (int it = 0; it < T; it++) {
        int cur = it & 1;
        sts(cur);
        if (it + 1 < T) ldg((it + 1) * 32);
        __syncthreads();

        #pragma unroll
        for (int ks = 0; ks < 2; ks++) {
            uint32_t aB = asu[cur] + ks * 32, bB = bsu[cur] + ks * 32;
            uint32_t af[4][4], bfr[4][4];
            #pragma unroll
            for (int mi = 0; mi < 4; mi++)
                LDSM4(af[mi][0], af[mi][1], af[mi][2], af[mi][3], aB + a_off + mi * (16 * 80));
            #pragma unroll
            for (int p = 0; p < 4; p++)
                LDSM4(bfr[p][0], bfr[p][1], bfr[p][2], bfr[p][3], bB + b_off + p * (16 * 80));
            #pragma unroll
            for (int mi = 0; mi < 4; mi++)
                #pragma unroll
                for (int ni = 0; ni < 8; ni++)
                    mma_f16(acc[mi][ni], af[mi][0], af[mi][1], af[mi][2], af[mi][3],
                            bfr[ni >> 1][(ni & 1) * 2], bfr[ni >> 1][(ni & 1) * 2 + 1]);
        }
    }

    #pragma unroll
    for (int mi = 0; mi < 4; mi++)
        #pragma unroll
        for (int ni = 0; ni < 8; ni++)
            #pragma unroll
            for (int h = 0; h < 2; h++) {
                int row = m0 + wm + mi * 16 + (lane >> 2) + h * 8;
                int col = n0 + wn + ni * 8 + 2 * (lane & 3);
                float inv = g_rowinv[b][row];
                float2 st;
                st.x = acc[mi][ni][2 * h + 0] * inv;
                st.y = acc[mi][ni][2 * h + 1] * inv;
                *(float2*)&g_ctx[b][row][col] = st;
            }
}

// ---------------- kernel 5: output projection (tf32 mma, round-9 verbatim) -
__global__ __launch_bounds__(256) void k_out(
    const float* __restrict__ Wo, float* __restrict__ out)
{
    __shared__ float As[2][64 * 20];
    __shared__ float Bs[2][16 * 136];

    const int n0 = blockIdx.x * 128;
    const int b  = blockIdx.y;
    const int t = threadIdx.x, lane = t & 31, warp = t >> 5;
    const int wn = warp * 16;

    const int a_e = t >> 2,  a_k  = (t & 3) * 4;
    const int b_cc = t >> 5, b_nn = (t & 31) * 4;

    float4 fa, fb0, fb1;
    auto ldg = [&](int c0) {
        fa  = *(const float4*)&Wo[(size_t)a_e * CC + c0 + a_k];
        fb0 = *(const float4*)&g_ctx[b][c0 + b_cc][n0 + b_nn];
        fb1 = *(const float4*)&g_ctx[b][c0 + b_cc + 8][n0 + b_nn];
    };
    auto sts = [&](int buf) {
        float4 ca;
        ca.x = tf32f(fa.x); ca.y = tf32f(fa.y); ca.z = tf32f(fa.z); ca.w = tf32f(fa.w);
        *(float4*)&As[buf][a_e * 20 + a_k] = ca;
        float4 c0v, c1v;
        c0v.x = tf32f(fb0.x); c0v.y = tf32f(fb0.y); c0v.z = tf32f(fb0.z); c0v.w = tf32f(fb0.w);
        c1v.x = tf32f(fb1.x); c1v.y = tf32f(fb1.y); c1v.z = tf32f(fb1.z); c1v.w = tf32f(fb1.w);
        *(float4*)&Bs[buf][b_cc * 136 + b_nn] = c0v;
        *(float4*)&Bs[buf][(b_cc + 8) * 136 + b_nn] = c1v;
    };

    float acc[4][2][4] = {};
    constexpr int T = CC / 16;
    ldg(0);

    for (int it = 0; it < T; it++) {
        int cur = it & 1;
        sts(cur);
        if (it + 1 < T) ldg((it + 1) * 16);
        __syncthreads();

        const float* A_ = As[cur];
        const float* B_ = Bs[cur];
        #pragma unroll
        for (int ks = 0; ks < 16; ks += 8) {
            int kk = ks + (lane & 3);
            uint32_t af[4][4], bf[2][2];
            #pragma unroll
            for (int mi = 0; mi < 4; mi++) {
                int m = mi * 16 + (lane >> 2);
                af[mi][0] = __float_as_uint(A_[m * 20 + kk]);
                af[mi][1] = __float_as_uint(A_[(m + 8) * 20 + kk]);
                af[mi][2] = __float_as_uint(A_[m * 20 + kk + 4]);
                af[mi][3] = __float_as_uint(A_[(m + 8) * 20 + kk + 4]);
            }
            #pragma unroll
            for (int ni = 0; ni < 2; ni++) {
                int n = wn + ni * 8 + (lane >> 2);
                bf[ni][0] = __float_as_uint(B_[kk * 136 + n]);
                bf[ni][1] = __float_as_uint(B_[(kk + 4) * 136 + n]);
            }
            #pragma unroll
            for (int mi = 0; mi < 4; mi++)
                #pragma unroll
                for (int ni = 0; ni < 2; ni++)
                    mma_tf32(acc[mi][ni], af[mi][0], af[mi][1], af[mi][2], af[mi][3],
                             bf[ni][0], bf[ni][1]);
        }
    }

    #pragma unroll
    for (int mi = 0; mi < 4; mi++)
        #pragma unroll
        for (int ni = 0; ni < 2; ni++)
            #pragma unroll
            for (int h = 0; h < 2; h++) {
                int e = mi * 16 + (lane >> 2) + h * 8;
                int n = n0 + wn + ni * 8 + 2 * (lane & 3);
                out[((size_t)b * NN + n) * EE + e]       = acc[mi][ni][2 * h + 0];
                out[((size_t)b * NN + n + 1) * EE + e]   = acc[mi][ni][2 * h + 1];
            }
}

// ---------------- launch ---------------------------------------------------
extern "C" void kernel_launch(void* const* d_in, const int* in_sizes, int n_in,
                              void* d_out, int out_size)
{
    const float* emb = (const float*)d_in[0];
    const float* Wq  = (const float*)d_in[1];
    const float* Wk  = (const float*)d_in[2];
    const float* Wv  = (const float*)d_in[3];
    const float* Wo  = (const float*)d_in[4];
    float* out = (float*)d_out;

    dim3 g1(16, 8, 24);
    k_proj<<<g1, 256>>>(emb, Wq, Wk, Wv);

    dim3 g2(CC / 128, DD / 128, BB);     // 4 x 32 x 8 = 1024 blocks
    k_scores<<<g2, 128>>>();

    dim3 g3(512, 8);
    k_softmax<<<g3, 128>>>();

    dim3 g4(CC / 128, NN / 128, BB);     // 4 x 8 x 8 = 256 blocks
    k_ctx<<<g4, 128>>>();

    dim3 g5(NN / 128, BB);               // 8 x 8
    k_out<<<g5, 256>>>(Wo, out);
}

// round 13
// speedup vs baseline: 1.2599x; 1.0965x over previous
#include <cuda_runtime.h>
#include <cuda_fp16.h>
#include <cstdint>

// Problem constants
#define BB 8        // half-batch
#define NN 1024     // sequence length
#define EE 64       // embedding channels
#define CC 512      // CH
#define DD 4096     // BB * CC
#define EPS_LN 1e-5f

// GEMM smem geometry: KTILE=64, rows of 144B (64 halfs + 8 pad halfs)
#define ROWB 144
#define A_STAGE (128 * ROWB)               // 18432 B
#define STAGE_B (2 * A_STAGE)              // 36864 B (A + B)
#define DSMEM (2 * STAGE_B)                // 73728 B, 2 stages

// ---------------- scratch (__device__ globals) ----------------------------
__device__ __half g_qTh[BB][CC][NN];      // A of scores: [c][n], k=n contig
__device__ __half g_kTh[DD][NN];          // B of scores: [d][n], k=n contig
__device__ __half g_vh[NN][DD];           // B of ctx:    [n][d], k=d contig
__device__ __half g_sch[BB][CC][DD];      // scores fp16, then exp() in-place
__device__ float  g_ctx[BB][CC][NN];      // fp32 [c][n]
__device__ float  g_sum[BB];
__device__ float  g_sumsq[BB];
__device__ float  g_rowinv[BB][CC];

// ---------------- helpers -------------------------------------------------
__device__ __forceinline__ void mma_f16(float c[4],
    uint32_t a0, uint32_t a1, uint32_t a2, uint32_t a3,
    uint32_t b0, uint32_t b1)
{
    asm volatile(
        "mma.sync.aligned.m16n8k16.row.col.f32.f16.f16.f32 "
        "{%0,%1,%2,%3},{%4,%5,%6,%7},{%8,%9},{%0,%1,%2,%3};"
        : "+f"(c[0]), "+f"(c[1]), "+f"(c[2]), "+f"(c[3])
        : "r"(a0), "r"(a1), "r"(a2), "r"(a3), "r"(b0), "r"(b1));
}

__device__ __forceinline__ void mma_tf32(float c[4],
    uint32_t a0, uint32_t a1, uint32_t a2, uint32_t a3,
    uint32_t b0, uint32_t b1)
{
    asm volatile(
        "mma.sync.aligned.m16n8k8.row.col.f32.tf32.tf32.f32 "
        "{%0,%1,%2,%3},{%4,%5,%6,%7},{%8,%9},{%0,%1,%2,%3};"
        : "+f"(c[0]), "+f"(c[1]), "+f"(c[2]), "+f"(c[3])
        : "r"(a0), "r"(a1), "r"(a2), "r"(a3), "r"(b0), "r"(b1));
}

#define LDSM4(d0, d1, d2, d3, addr) \
    asm volatile("ldmatrix.sync.aligned.m8n8.x4.shared.b16 {%0,%1,%2,%3}, [%4];" \
        : "=r"(d0), "=r"(d1), "=r"(d2), "=r"(d3) : "r"(addr))

__device__ __forceinline__ uint32_t tf32u(float x) {
    uint32_t u; asm("cvt.rna.tf32.f32 %0, %1;" : "=r"(u) : "f"(x)); return u;
}
__device__ __forceinline__ float tf32f(float x) { return __uint_as_float(tf32u(x)); }

__device__ __forceinline__ uint32_t smem_u32(const void* p) {
    uint32_t a;
    asm("{ .reg .u64 t; cvta.to.shared.u64 t, %1; cvt.u32.u64 %0, t; }" : "=r"(a) : "l"(p));
    return a;
}
__device__ __forceinline__ void cpa16(uint32_t dst, const void* src) {
    asm volatile("cp.async.cg.shared.global [%0], [%1], 16;" :: "r"(dst), "l"(src));
}
__device__ __forceinline__ void cp_commit() {
    asm volatile("cp.async.commit_group;" ::: "memory");
}
__device__ __forceinline__ void cp_wait_all() {
    asm volatile("cp.async.wait_group 0;" ::: "memory");
}

// ---------------- kernel 1: q/k/v projections (round-9 verbatim) ----------
__global__ __launch_bounds__(256) void k_proj(
    const float* __restrict__ emb, const float* __restrict__ Wq,
    const float* __restrict__ Wk,  const float* __restrict__ Wv)
{
    __shared__ float embS[64][68];
    __shared__ float WS[64][68];
    __shared__ __half transS[64][72];

    int ntile = blockIdx.x, ctile = blockIdx.y, bz = blockIdx.z;
    int b = bz / 3, m = bz % 3;
    const float* W  = (m == 0) ? Wq : ((m == 1) ? Wk : Wv);
    const float* eb = emb + (size_t)((m == 0) ? (BB + b) : b) * NN * EE;
    int n0 = ntile * 64, c0 = ctile * 64;
    int t = threadIdx.x;

    if (ntile == 0 && ctile == 0 && bz == 0 && t < BB) {
        g_sum[t] = 0.f; g_sumsq[t] = 0.f;
    }

    #pragma unroll
    for (int r = 0; r < 4; r++) {
        int chunk = t + 256 * r;
        int row = chunk >> 4;
        int col = (chunk & 15) * 4;
        *(float4*)&embS[row][col] = *(const float4*)&eb[(size_t)(n0 + row) * EE + col];
        *(float4*)&WS[row][col]   = *(const float4*)&W[(size_t)(c0 + row) * EE + col];
    }
    __syncthreads();

    int ty = t >> 4, tx = t & 15;
    float acc[4][4] = {};
    #pragma unroll 16
    for (int e = 0; e < 64; e++) {
        float a[4], bv[4];
        #pragma unroll
        for (int i = 0; i < 4; i++) a[i]  = embS[ty + 16 * i][e];
        #pragma unroll
        for (int j = 0; j < 4; j++) bv[j] = WS[tx + 16 * j][e];
        #pragma unroll
        for (int i = 0; i < 4; i++)
            #pragma unroll
            for (int j = 0; j < 4; j++) acc[i][j] += a[i] * bv[j];
    }

    if (m == 2) {
        #pragma unroll
        for (int i = 0; i < 4; i++)
            #pragma unroll
            for (int j = 0; j < 4; j++)
                g_vh[n0 + ty + 16 * i][b * CC + c0 + tx + 16 * j] = __float2half_rn(acc[i][j]);
        return;
    }

    #pragma unroll
    for (int i = 0; i < 4; i++)
        #pragma unroll
        for (int j = 0; j < 4; j++)
            transS[tx + 16 * j][ty + 16 * i] = __float2half_rn(acc[i][j]);
    __syncthreads();

    int cl = t >> 2, g = t & 3;
    uint4 v0 = *(const uint4*)&transS[cl][g * 16];
    uint4 v1 = *(const uint4*)&transS[cl][g * 16 + 8];
    __half* dst = (m == 0) ? &g_qTh[b][c0 + cl][n0 + g * 16]
                           : &g_kTh[b * CC + c0 + cl][n0 + g * 16];
    *(uint4*)dst = v0;
    *(uint4*)(dst + 8) = v1;
}

// ---------------- kernel 2: scores GEMM (KTILE=64, cp.async, dyn smem) -----
// 128x128 block, 4 warps of 64x64, 2 CTAs/SM. Rows 144B: LDSM conflict-free.
__global__ __launch_bounds__(128, 2) void k_scores()
{
    extern __shared__ __align__(16) char dsm[];

    const int m0 = blockIdx.x * 128, n0 = blockIdx.y * 128, b = blockIdx.z;
    const int t = threadIdx.x, lane = t & 31, warp = t >> 5;
    const int wm = (warp & 1) * 64, wn = (warp >> 1) * 64;

    const __half* A  = &g_qTh[b][m0][0];
    const __half* Bp = &g_kTh[n0][0];
    const uint32_t sbase = smem_u32(dsm);

    auto issue = [&](int st) {
        uint32_t sb = sbase + (st & 1) * STAGE_B;
        int k0 = st * 64;
        #pragma unroll
        for (int i = 0; i < 8; i++) {
            int ch = t + 128 * i;
            int row = ch >> 3, c = ch & 7;
            cpa16(sb + row * ROWB + c * 16,           A  + (size_t)row * NN + k0 + c * 8);
            cpa16(sb + A_STAGE + row * ROWB + c * 16, Bp + (size_t)row * NN + k0 + c * 8);
        }
        cp_commit();
    };

    const int g = lane >> 3, r8 = lane & 7;
    const uint32_t a_off = (uint32_t)((wm + ((g & 1) << 3) + r8) * ROWB + ((g >> 1) << 4));
    const uint32_t b_off = (uint32_t)((wn + ((g >> 1) << 3) + r8) * ROWB + ((g & 1) << 4));

    float acc[4][8][4] = {};
    constexpr int T = NN / 64;
    issue(0);

    for (int it = 0; it < T; it++) {
        cp_wait_all();
        __syncthreads();
        if (it + 1 < T) issue(it + 1);

        uint32_t stg = sbase + (it & 1) * STAGE_B;
        #pragma unroll
        for (int ks = 0; ks < 4; ks++) {
            uint32_t aB = stg + ks * 32, bB = stg + A_STAGE + ks * 32;
            uint32_t af[4][4], bfr[4][4];
            #pragma unroll
            for (int mi = 0; mi < 4; mi++)
                LDSM4(af[mi][0], af[mi][1], af[mi][2], af[mi][3], aB + a_off + mi * (16 * ROWB));
            #pragma unroll
            for (int p = 0; p < 4; p++)
                LDSM4(bfr[p][0], bfr[p][1], bfr[p][2], bfr[p][3], bB + b_off + p * (16 * ROWB));
            #pragma unroll
            for (int mi = 0; mi < 4; mi++)
                #pragma unroll
                for (int ni = 0; ni < 8; ni++)
                    mma_f16(acc[mi][ni], af[mi][0], af[mi][1], af[mi][2], af[mi][3],
                            bfr[ni >> 1][(ni & 1) * 2], bfr[ni >> 1][(ni & 1) * 2 + 1]);
        }
    }

    // epilogue: fp16 scores; stats via warp shuffle + 1 atomic per warp
    float ls = 0.f, lq = 0.f;
    #pragma unroll
    for (int mi = 0; mi < 4; mi++)
        #pragma unroll
        for (int ni = 0; ni < 8; ni++)
            #pragma unroll
            for (int h = 0; h < 2; h++) {
                int row = m0 + wm + mi * 16 + (lane >> 2) + h * 8;
                int col = n0 + wn + ni * 8 + 2 * (lane & 3);
                float v0 = acc[mi][ni][2 * h + 0];
                float v1 = acc[mi][ni][2 * h + 1];
                *(__half2*)&g_sch[b][row][col] = __floats2half2_rn(v0, v1);
                ls += v0 + v1;
                lq += v0 * v0 + v1 * v1;
            }

    #pragma unroll
    for (int o = 16; o > 0; o >>= 1) {
        ls += __shfl_xor_sync(0xffffffffu, ls, o);
        lq += __shfl_xor_sync(0xffffffffu, lq, o);
    }
    if (lane == 0) {
        atomicAdd(&g_sum[b], ls);
        atomicAdd(&g_sumsq[b], lq);
    }
}

// ---------------- kernel 3: LN + exp (in-place, half) + row-sum -----------
__global__ __launch_bounds__(128) void k_softmax()
{
    int c = blockIdx.x, b = blockIdx.y;
    int t = threadIdx.x, lane = t & 31, warp = t >> 5;
    __shared__ float red[4];

    const float invCD = 1.0f / ((float)CC * (float)DD);
    float mean = g_sum[b] * invCD;
    float var  = g_sumsq[b] * invCD - mean * mean;
    float rstd = rsqrtf(var + EPS_LN);

    __half* row = &g_sch[b][c][0];
    float ls = 0.f;
    #pragma unroll
    for (int r = 0; r < 4; r++) {
        int idx = (t + 128 * r) * 8;
        uint4 v = *(const uint4*)&row[idx];
        __half2* hp = (__half2*)&v;
        #pragma unroll
        for (int j = 0; j < 4; j++) {
            float2 f = __half22float2(hp[j]);
            f.x = __expf((f.x - mean) * rstd);
            f.y = __expf((f.y - mean) * rstd);
            ls += f.x + f.y;
            hp[j] = __floats2half2_rn(f.x, f.y);
        }
        *(uint4*)&row[idx] = v;
    }
    #pragma unroll
    for (int o = 16; o > 0; o >>= 1) ls += __shfl_xor_sync(0xffffffffu, ls, o);
    if (lane == 0) red[warp] = ls;
    __syncthreads();
    if (t == 0) g_rowinv[b][c] = 1.0f / (red[0] + red[1] + red[2] + red[3]);
}

// ---------------- kernel 4: ctx GEMM (KTILE=64, cp.async, dyn smem) --------
__global__ __launch_bounds__(128, 2) void k_ctx()
{
    extern __shared__ __align__(16) char dsm[];

    const int m0 = blockIdx.x * 128, n0 = blockIdx.y * 128, b = blockIdx.z;
    const int t = threadIdx.x, lane = t & 31, warp = t >> 5;
    const int wm = (warp & 1) * 64, wn = (warp >> 1) * 64;

    const __half* A  = &g_sch[b][m0][0];
    const __half* Bp = &g_vh[n0][0];
    const uint32_t sbase = smem_u32(dsm);

    auto issue = [&](int st) {
        uint32_t sb = sbase + (st & 1) * STAGE_B;
        int k0 = st * 64;
        #pragma unroll
        for (int i = 0; i < 8; i++) {
            int ch = t + 128 * i;
            int row = ch >> 3, c = ch & 7;
            cpa16(sb + row * ROWB + c * 16,           A  + (size_t)row * DD + k0 + c * 8);
            cpa16(sb + A_STAGE + row * ROWB + c * 16, Bp + (size_t)row * DD + k0 + c * 8);
        }
        cp_commit();
    };

    const int g = lane >> 3, r8 = lane & 7;
    const uint32_t a_off = (uint32_t)((wm + ((g & 1) << 3) + r8) * ROWB + ((g >> 1) << 4));
    const uint32_t b_off = (uint32_t)((wn + ((g >> 1) << 3) + r8) * ROWB + ((g & 1) << 4));

    float acc[4][8][4] = {};
    constexpr int T = DD / 64;
    issue(0);

    for (int it = 0; it < T; it++) {
        cp_wait_all();
        __syncthreads();
        if (it + 1 < T) issue(it + 1);

        uint32_t stg = sbase + (it & 1) * STAGE_B;
        #pragma unroll
        for (int ks = 0; ks < 4; ks++) {
            uint32_t aB = stg + ks * 32, bB = stg + A_STAGE + ks * 32;
            uint32_t af[4][4], bfr[4][4];
            #pragma unroll
            for (int mi = 0; mi < 4; mi++)
                LDSM4(af[mi][0], af[mi][1], af[mi][2], af[mi][3], aB + a_off + mi * (16 * ROWB));
            #pragma unroll
            for (int p = 0; p < 4; p++)
                LDSM4(bfr[p][0], bfr[p][1], bfr[p][2], bfr[p][3], bB + b_off + p * (16 * ROWB));
            #pragma unroll
            for (int mi = 0; mi < 4; mi++)
                #pragma unroll
                for (int ni = 0; ni < 8; ni++)
                    mma_f16(acc[mi][ni], af[mi][0], af[mi][1], af[mi][2], af[mi][3],
                            bfr[ni >> 1][(ni & 1) * 2], bfr[ni >> 1][(ni & 1) * 2 + 1]);
        }
    }

    #pragma unroll
    for (int mi = 0; mi < 4; mi++)
        #pragma unroll
        for (int ni = 0; ni < 8; ni++)
            #pragma unroll
            for (int h = 0; h < 2; h++) {
                int row = m0 + wm + mi * 16 + (lane >> 2) + h * 8;
                int col = n0 + wn + ni * 8 + 2 * (lane & 3);
                float inv = g_rowinv[b][row];
                float2 st;
                st.x = acc[mi][ni][2 * h + 0] * inv;
                st.y = acc[mi][ni][2 * h + 1] * inv;
                *(float2*)&g_ctx[b][row][col] = st;
            }
}

// ---------------- kernel 5: output projection (tf32 mma, round-9 verbatim) -
__global__ __launch_bounds__(256) void k_out(
    const float* __restrict__ Wo, float* __restrict__ out)
{
    __shared__ float As[2][64 * 20];
    __shared__ float Bs[2][16 * 136];

    const int n0 = blockIdx.x * 128;
    const int b  = blockIdx.y;
    const int t = threadIdx.x, lane = t & 31, warp = t >> 5;
    const int wn = warp * 16;

    const int a_e = t >> 2,  a_k  = (t & 3) * 4;
    const int b_cc = t >> 5, b_nn = (t & 31) * 4;

    float4 fa, fb0, fb1;
    auto ldg = [&](int c0) {
        fa  = *(const float4*)&Wo[(size_t)a_e * CC + c0 + a_k];
        fb0 = *(const float4*)&g_ctx[b][c0 + b_cc][n0 + b_nn];
        fb1 = *(const float4*)&g_ctx[b][c0 + b_cc + 8][n0 + b_nn];
    };
    auto sts = [&](int buf) {
        float4 ca;
        ca.x = tf32f(fa.x); ca.y = tf32f(fa.y); ca.z = tf32f(fa.z); ca.w = tf32f(fa.w);
        *(float4*)&As[buf][a_e * 20 + a_k] = ca;
        float4 c0v, c1v;
        c0v.x = tf32f(fb0.x); c0v.y = tf32f(fb0.y); c0v.z = tf32f(fb0.z); c0v.w = tf32f(fb0.w);
        c1v.x = tf32f(fb1.x); c1v.y = tf32f(fb1.y); c1v.z = tf32f(fb1.z); c1v.w = tf32f(fb1.w);
        *(float4*)&Bs[buf][b_cc * 136 + b_nn] = c0v;
        *(float4*)&Bs[buf][(b_cc + 8) * 136 + b_nn] = c1v;
    };

    float acc[4][2][4] = {};
    constexpr int T = CC / 16;
    ldg(0);

    for (int it = 0; it < T; it++) {
        int cur = it & 1;
        sts(cur);
        if (it + 1 < T) ldg((it + 1) * 16);
        __syncthreads();

        const float* A_ = As[cur];
        const float* B_ = Bs[cur];
        #pragma unroll
        for (int ks = 0; ks < 16; ks += 8) {
            int kk = ks + (lane & 3);
            uint32_t af[4][4], bf[2][2];
            #pragma unroll
            for (int mi = 0; mi < 4; mi++) {
                int m = mi * 16 + (lane >> 2);
                af[mi][0] = __float_as_uint(A_[m * 20 + kk]);
                af[mi][1] = __float_as_uint(A_[(m + 8) * 20 + kk]);
                af[mi][2] = __float_as_uint(A_[m * 20 + kk + 4]);
                af[mi][3] = __float_as_uint(A_[(m + 8) * 20 + kk + 4]);
            }
            #pragma unroll
            for (int ni = 0; ni < 2; ni++) {
                int n = wn + ni * 8 + (lane >> 2);
                bf[ni][0] = __float_as_uint(B_[kk * 136 + n]);
                bf[ni][1] = __float_as_uint(B_[(kk + 4) * 136 + n]);
            }
            #pragma unroll
            for (int mi = 0; mi < 4; mi++)
                #pragma unroll
                for (int ni = 0; ni < 2; ni++)
                    mma_tf32(acc[mi][ni], af[mi][0], af[mi][1], af[mi][2], af[mi][3],
                             bf[ni][0], bf[ni][1]);
        }
    }

    #pragma unroll
    for (int mi = 0; mi < 4; mi++)
        #pragma unroll
        for (int ni = 0; ni < 2; ni++)
            #pragma unroll
            for (int h = 0; h < 2; h++) {
                int e = mi * 16 + (lane >> 2) + h * 8;
                int n = n0 + wn + ni * 8 + 2 * (lane & 3);
                out[((size_t)b * NN + n) * EE + e]       = acc[mi][ni][2 * h + 0];
                out[((size_t)b * NN + n + 1) * EE + e]   = acc[mi][ni][2 * h + 1];
            }
}

// ---------------- launch ---------------------------------------------------
extern "C" void kernel_launch(void* const* d_in, const int* in_sizes, int n_in,
                              void* d_out, int out_size)
{
    const float* emb = (const float*)d_in[0];
    const float* Wq  = (const float*)d_in[1];
    const float* Wk  = (const float*)d_in[2];
    const float* Wv  = (const float*)d_in[3];
    const float* Wo  = (const float*)d_in[4];
    float* out = (float*)d_out;

    static bool attr_done = false;
    if (!attr_done) {
        cudaFuncSetAttribute(k_scores, cudaFuncAttributeMaxDynamicSharedMemorySize, DSMEM);
        cudaFuncSetAttribute(k_ctx,    cudaFuncAttributeMaxDynamicSharedMemorySize, DSMEM);
        attr_done = true;
    }

    dim3 g1(16, 8, 24);
    k_proj<<<g1, 256>>>(emb, Wq, Wk, Wv);

    dim3 g2(CC / 128, DD / 128, BB);     // 4 x 32 x 8 = 1024 blocks
    k_scores<<<g2, 128, DSMEM>>>();

    dim3 g3(512, 8);
    k_softmax<<<g3, 128>>>();

    dim3 g4(CC / 128, NN / 128, BB);     // 4 x 8 x 8 = 256 blocks
    k_ctx<<<g4, 128, DSMEM>>>();

    dim3 g5(NN / 128, BB);               // 8 x 8
    k_out<<<g5, 256>>>(Wo, out);
}

// round 15
// speedup vs baseline: 1.2805x; 1.0164x over previous
#include <cuda_runtime.h>
#include <cuda_fp16.h>
#include <cstdint>

// Problem constants
#define BB 8        // half-batch
#define NN 1024     // sequence length
#define EE 64       // embedding channels
#define CC 512      // CH
#define DD 4096     // BB * CC
#define EPS_LN 1e-5f

// GEMM smem geometry: KTILE=64, rows of 144B (64 halfs + 8 pad halfs)
#define ROWB 144
#define A_STAGE (128 * ROWB)               // 18432 B
#define STAGE_B (2 * A_STAGE)              // 36864 B (A + B)
#define DSMEM (2 * STAGE_B)                // 73728 B, 2 stages

// ---------------- scratch (__device__ globals) ----------------------------
__device__ __half g_qTh[BB][CC][NN];      // A of scores: [c][n], k=n contig
__device__ __half g_kTh[DD][NN];          // B of scores: [d][n], k=n contig
__device__ __half g_vh[NN][DD];           // B of ctx:    [n][d], k=d contig
__device__ __half g_sch[BB][CC][DD];      // scores fp16, then exp() in-place
__device__ float  g_ctx[BB][CC][NN];      // fp32 [c][n]
__device__ float  g_sum[BB];
__device__ float  g_sumsq[BB];
__device__ float  g_rowinv[BB][CC];

// ---------------- helpers -------------------------------------------------
__device__ __forceinline__ void mma_f16(float c[4],
    uint32_t a0, uint32_t a1, uint32_t a2, uint32_t a3,
    uint32_t b0, uint32_t b1)
{
    asm volatile(
        "mma.sync.aligned.m16n8k16.row.col.f32.f16.f16.f32 "
        "{%0,%1,%2,%3},{%4,%5,%6,%7},{%8,%9},{%0,%1,%2,%3};"
        : "+f"(c[0]), "+f"(c[1]), "+f"(c[2]), "+f"(c[3])
        : "r"(a0), "r"(a1), "r"(a2), "r"(a3), "r"(b0), "r"(b1));
}

__device__ __forceinline__ void mma_tf32(float c[4],
    uint32_t a0, uint32_t a1, uint32_t a2, uint32_t a3,
    uint32_t b0, uint32_t b1)
{
    asm volatile(
        "mma.sync.aligned.m16n8k8.row.col.f32.tf32.tf32.f32 "
        "{%0,%1,%2,%3},{%4,%5,%6,%7},{%8,%9},{%0,%1,%2,%3};"
        : "+f"(c[0]), "+f"(c[1]), "+f"(c[2]), "+f"(c[3])
        : "r"(a0), "r"(a1), "r"(a2), "r"(a3), "r"(b0), "r"(b1));
}

#define LDSM4(d0, d1, d2, d3, addr) \
    asm volatile("ldmatrix.sync.aligned.m8n8.x4.shared.b16 {%0,%1,%2,%3}, [%4];" \
        : "=r"(d0), "=r"(d1), "=r"(d2), "=r"(d3) : "r"(addr))

__device__ __forceinline__ uint32_t tf32u(float x) {
    uint32_t u; asm("cvt.rna.tf32.f32 %0, %1;" : "=r"(u) : "f"(x)); return u;
}
__device__ __forceinline__ float tf32f(float x) { return __uint_as_float(tf32u(x)); }

__device__ __forceinline__ uint32_t smem_u32(const void* p) {
    uint32_t a;
    asm("{ .reg .u64 t; cvta.to.shared.u64 t, %1; cvt.u32.u64 %0, t; }" : "=r"(a) : "l"(p));
    return a;
}
__device__ __forceinline__ void cpa16(uint32_t dst, const void* src) {
    asm volatile("cp.async.cg.shared.global [%0], [%1], 16;" :: "r"(dst), "l"(src));
}
__device__ __forceinline__ void cp_commit() {
    asm volatile("cp.async.commit_group;" ::: "memory");
}
__device__ __forceinline__ void cp_wait_all() {
    asm volatile("cp.async.wait_group 0;" ::: "memory");
}

// ---------------- kernel 1: q/k/v projections (round-9 verbatim) ----------
__global__ __launch_bounds__(256) void k_proj(
    const float* __restrict__ emb, const float* __restrict__ Wq,
    const float* __restrict__ Wk,  const float* __restrict__ Wv)
{
    __shared__ float embS[64][68];
    __shared__ float WS[64][68];
    __shared__ __half transS[64][72];

    int ntile = blockIdx.x, ctile = blockIdx.y, bz = blockIdx.z;
    int b = bz / 3, m = bz % 3;
    const float* W  = (m == 0) ? Wq : ((m == 1) ? Wk : Wv);
    const float* eb = emb + (size_t)((m == 0) ? (BB + b) : b) * NN * EE;
    int n0 = ntile * 64, c0 = ctile * 64;
    int t = threadIdx.x;

    if (ntile == 0 && ctile == 0 && bz == 0 && t < BB) {
        g_sum[t] = 0.f; g_sumsq[t] = 0.f;
    }

    #pragma unroll
    for (int r = 0; r < 4; r++) {
        int chunk = t + 256 * r;
        int row = chunk >> 4;
        int col = (chunk & 15) * 4;
        *(float4*)&embS[row][col] = *(const float4*)&eb[(size_t)(n0 + row) * EE + col];
        *(float4*)&WS[row][col]   = *(const float4*)&W[(size_t)(c0 + row) * EE + col];
    }
    __syncthreads();

    int ty = t >> 4, tx = t & 15;
    float acc[4][4] = {};
    #pragma unroll 16
    for (int e = 0; e < 64; e++) {
        float a[4], bv[4];
        #pragma unroll
        for (int i = 0; i < 4; i++) a[i]  = embS[ty + 16 * i][e];
        #pragma unroll
        for (int j = 0; j < 4; j++) bv[j] = WS[tx + 16 * j][e];
        #pragma unroll
        for (int i = 0; i < 4; i++)
            #pragma unroll
            for (int j = 0; j < 4; j++) acc[i][j] += a[i] * bv[j];
    }

    if (m == 2) {
        #pragma unroll
        for (int i = 0; i < 4; i++)
            #pragma unroll
            for (int j = 0; j < 4; j++)
                g_vh[n0 + ty + 16 * i][b * CC + c0 + tx + 16 * j] = __float2half_rn(acc[i][j]);
        return;
    }

    #pragma unroll
    for (int i = 0; i < 4; i++)
        #pragma unroll
        for (int j = 0; j < 4; j++)
            transS[tx + 16 * j][ty + 16 * i] = __float2half_rn(acc[i][j]);
    __syncthreads();

    int cl = t >> 2, g = t & 3;
    uint4 v0 = *(const uint4*)&transS[cl][g * 16];
    uint4 v1 = *(const uint4*)&transS[cl][g * 16 + 8];
    __half* dst = (m == 0) ? &g_qTh[b][c0 + cl][n0 + g * 16]
                           : &g_kTh[b * CC + c0 + cl][n0 + g * 16];
    *(uint4*)dst = v0;
    *(uint4*)(dst + 8) = v1;
}

// ---------------- kernel 2: scores GEMM ------------------------------------
// 128x128 block, 256 threads, 8 warps (2m x 4n) of 64x32; KTILE=64 cp.async.
__global__ __launch_bounds__(256, 2) void k_scores()
{
    extern __shared__ __align__(16) char dsm[];

    const int m0 = blockIdx.x * 128, n0 = blockIdx.y * 128, b = blockIdx.z;
    const int t = threadIdx.x, lane = t & 31, warp = t >> 5;
    const int wm = (warp & 1) * 64, wn = (warp >> 1) * 32;

    const __half* A  = &g_qTh[b][m0][0];
    const __half* Bp = &g_kTh[n0][0];
    const uint32_t sbase = smem_u32(dsm);

    auto issue = [&](int st) {
        uint32_t sb = sbase + (st & 1) * STAGE_B;
        int k0 = st * 64;
        #pragma unroll
        for (int i = 0; i < 4; i++) {
            int ch = t + 256 * i;
            int row = ch >> 3, c = ch & 7;
            cpa16(sb + row * ROWB + c * 16,           A  + (size_t)row * NN + k0 + c * 8);
            cpa16(sb + A_STAGE + row * ROWB + c * 16, Bp + (size_t)row * NN + k0 + c * 8);
        }
        cp_commit();
    };

    const int g = lane >> 3, r8 = lane & 7;
    const uint32_t a_off = (uint32_t)((wm + ((g & 1) << 3) + r8) * ROWB + ((g >> 1) << 4));
    const uint32_t b_off = (uint32_t)((wn + ((g >> 1) << 3) + r8) * ROWB + ((g & 1) << 4));

    float acc[4][4][4] = {};
    constexpr int T = NN / 64;
    issue(0);

    for (int it = 0; it < T; it++) {
        cp_wait_all();
        __syncthreads();
        if (it + 1 < T) issue(it + 1);

        uint32_t stg = sbase + (it & 1) * STAGE_B;
        #pragma unroll
        for (int ks = 0; ks < 4; ks++) {
            uint32_t aB = stg + ks * 32, bB = stg + A_STAGE + ks * 32;
            uint32_t af[4][4], bfr[2][4];
            #pragma unroll
            for (int mi = 0; mi < 4; mi++)
                LDSM4(af[mi][0], af[mi][1], af[mi][2], af[mi][3], aB + a_off + mi * (16 * ROWB));
            #pragma unroll
            for (int p = 0; p < 2; p++)
                LDSM4(bfr[p][0], bfr[p][1], bfr[p][2], bfr[p][3], bB + b_off + p * (16 * ROWB));
            #pragma unroll
            for (int mi = 0; mi < 4; mi++)
                #pragma unroll
                for (int ni = 0; ni < 4; ni++)
                    mma_f16(acc[mi][ni], af[mi][0], af[mi][1], af[mi][2], af[mi][3],
                            bfr[ni >> 1][(ni & 1) * 2], bfr[ni >> 1][(ni & 1) * 2 + 1]);
        }
    }

    // epilogue: fp16 scores; stats via warp shuffle + 1 atomic per warp
    float ls = 0.f, lq = 0.f;
    #pragma unroll
    for (int mi = 0; mi < 4; mi++)
        #pragma unroll
        for (int ni = 0; ni < 4; ni++)
            #pragma unroll
            for (int h = 0; h < 2; h++) {
                int row = m0 + wm + mi * 16 + (lane >> 2) + h * 8;
                int col = n0 + wn + ni * 8 + 2 * (lane & 3);
                float v0 = acc[mi][ni][2 * h + 0];
                float v1 = acc[mi][ni][2 * h + 1];
                *(__half2*)&g_sch[b][row][col] = __floats2half2_rn(v0, v1);
                ls += v0 + v1;
                lq += v0 * v0 + v1 * v1;
            }

    #pragma unroll
    for (int o = 16; o > 0; o >>= 1) {
        ls += __shfl_xor_sync(0xffffffffu, ls, o);
        lq += __shfl_xor_sync(0xffffffffu, lq, o);
    }
    if (lane == 0) {
        atomicAdd(&g_sum[b], ls);
        atomicAdd(&g_sumsq[b], lq);
    }
}

// ---------------- kernel 3: LN + exp (in-place, half) + row-sum -----------
__global__ __launch_bounds__(128) void k_softmax()
{
    int c = blockIdx.x, b = blockIdx.y;
    int t = threadIdx.x, lane = t & 31, warp = t >> 5;
    __shared__ float red[4];

    const float invCD = 1.0f / ((float)CC * (float)DD);
    float mean = g_sum[b] * invCD;
    float var  = g_sumsq[b] * invCD - mean * mean;
    float rstd = rsqrtf(var + EPS_LN);

    __half* row = &g_sch[b][c][0];
    float ls = 0.f;
    #pragma unroll
    for (int r = 0; r < 4; r++) {
        int idx = (t + 128 * r) * 8;
        uint4 v = *(const uint4*)&row[idx];
        __half2* hp = (__half2*)&v;
        #pragma unroll
        for (int j = 0; j < 4; j++) {
            float2 f = __half22float2(hp[j]);
            f.x = __expf((f.x - mean) * rstd);
            f.y = __expf((f.y - mean) * rstd);
            ls += f.x + f.y;
            hp[j] = __floats2half2_rn(f.x, f.y);
        }
        *(uint4*)&row[idx] = v;
    }
    #pragma unroll
    for (int o = 16; o > 0; o >>= 1) ls += __shfl_xor_sync(0xffffffffu, ls, o);
    if (lane == 0) red[warp] = ls;
    __syncthreads();
    if (t == 0) g_rowinv[b][c] = 1.0f / (red[0] + red[1] + red[2] + red[3]);
}

// ---------------- kernel 4: ctx GEMM ---------------------------------------
// Same 8-warp structure; A = exp(scores) half, B = vh, K = DD.
__global__ __launch_bounds__(256, 2) void k_ctx()
{
    extern __shared__ __align__(16) char dsm[];

    const int m0 = blockIdx.x * 128, n0 = blockIdx.y * 128, b = blockIdx.z;
    const int t = threadIdx.x, lane = t & 31, warp = t >> 5;
    const int wm = (warp & 1) * 64, wn = (warp >> 1) * 32;

    const __half* A  = &g_sch[b][m0][0];
    const __half* Bp = &g_vh[n0][0];
    const uint32_t sbase = smem_u32(dsm);

    auto issue = [&](int st) {
        uint32_t sb = sbase + (st & 1) * STAGE_B;
        int k0 = st * 64;
        #pragma unroll
        for (int i = 0; i < 4; i++) {
            int ch = t + 256 * i;
            int row = ch >> 3, c = ch & 7;
            cpa16(sb + row * ROWB + c * 16,           A  + (size_t)row * DD + k0 + c * 8);
            cpa16(sb + A_STAGE + row * ROWB + c * 16, Bp + (size_t)row * DD + k0 + c * 8);
        }
        cp_commit();
    };

    const int g = lane >> 3, r8 = lane & 7;
    const uint32_t a_off = (uint32_t)((wm + ((g & 1) << 3) + r8) * ROWB + ((g >> 1) << 4));
    const uint32_t b_off = (uint32_t)((wn + ((g >> 1) << 3) + r8) * ROWB + ((g & 1) << 4));

    float acc[4][4][4] = {};
    constexpr int T = DD / 64;
    issue(0);

    for (int it = 0; it < T; it++) {
        cp_wait_all();
        __syncthreads();
        if (it + 1 < T) issue(it + 1);

        uint32_t stg = sbase + (it & 1) * STAGE_B;
        #pragma unroll
        for (int ks = 0; ks < 4; ks++) {
            uint32_t aB = stg + ks * 32, bB = stg + A_STAGE + ks * 32;
            uint32_t af[4][4], bfr[2][4];
            #pragma unroll
            for (int mi = 0; mi < 4; mi++)
                LDSM4(af[mi][0], af[mi][1], af[mi][2], af[mi][3], aB + a_off + mi * (16 * ROWB));
            #pragma unroll
            for (int p = 0; p < 2; p++)
                LDSM4(bfr[p][0], bfr[p][1], bfr[p][2], bfr[p][3], bB + b_off + p * (16 * ROWB));
            #pragma unroll
            for (int mi = 0; mi < 4; mi++)
                #pragma unroll
                for (int ni = 0; ni < 4; ni++)
                    mma_f16(acc[mi][ni], af[mi][0], af[mi][1], af[mi][2], af[mi][3],
                            bfr[ni >> 1][(ni & 1) * 2], bfr[ni >> 1][(ni & 1) * 2 + 1]);
        }
    }

    #pragma unroll
    for (int mi = 0; mi < 4; mi++)
        #pragma unroll
        for (int ni = 0; ni < 4; ni++)
            #pragma unroll
            for (int h = 0; h < 2; h++) {
                int row = m0 + wm + mi * 16 + (lane >> 2) + h * 8;
                int col = n0 + wn + ni * 8 + 2 * (lane & 3);
                float inv = g_rowinv[b][row];
                float2 st;
                st.x = acc[mi][ni][2 * h + 0] * inv;
                st.y = acc[mi][ni][2 * h + 1] * inv;
                *(float2*)&g_ctx[b][row][col] = st;
            }
}

// ---------------- kernel 5: output projection (tf32 mma, round-9 verbatim) -
__global__ __launch_bounds__(256) void k_out(
    const float* __restrict__ Wo, float* __restrict__ out)
{
    __shared__ float As[2][64 * 20];
    __shared__ float Bs[2][16 * 136];

    const int n0 = blockIdx.x * 128;
    const int b  = blockIdx.y;
    const int t = threadIdx.x, lane = t & 31, warp = t >> 5;
    const int wn = warp * 16;

    const int a_e = t >> 2,  a_k  = (t & 3) * 4;
    const int b_cc = t >> 5, b_nn = (t & 31) * 4;

    float4 fa, fb0, fb1;
    auto ldg = [&](int c0) {
        fa  = *(const float4*)&Wo[(size_t)a_e * CC + c0 + a_k];
        fb0 = *(const float4*)&g_ctx[b][c0 + b_cc][n0 + b_nn];
        fb1 = *(const float4*)&g_ctx[b][c0 + b_cc + 8][n0 + b_nn];
    };
    auto sts = [&](int buf) {
        float4 ca;
        ca.x = tf32f(fa.x); ca.y = tf32f(fa.y); ca.z = tf32f(fa.z); ca.w = tf32f(fa.w);
        *(float4*)&As[buf][a_e * 20 + a_k] = ca;
        float4 c0v, c1v;
        c0v.x = tf32f(fb0.x); c0v.y = tf32f(fb0.y); c0v.z = tf32f(fb0.z); c0v.w = tf32f(fb0.w);
        c1v.x = tf32f(fb1.x); c1v.y = tf32f(fb1.y); c1v.z = tf32f(fb1.z); c1v.w = tf32f(fb1.w);
        *(float4*)&Bs[buf][b_cc * 136 + b_nn] = c0v;
        *(float4*)&Bs[buf][(b_cc + 8) * 136 + b_nn] = c1v;
    };

    float acc[4][2][4] = {};
    constexpr int T = CC / 16;
    ldg(0);

    for (int it = 0; it < T; it++) {
        int cur = it & 1;
        sts(cur);
        if (it + 1 < T) ldg((it + 1) * 16);
        __syncthreads();

        const float* A_ = As[cur];
        const float* B_ = Bs[cur];
        #pragma unroll
        for (int ks = 0; ks < 16; ks += 8) {
            int kk = ks + (lane & 3);
            uint32_t af[4][4], bf[2][2];
            #pragma unroll
            for (int mi = 0; mi < 4; mi++) {
                int m = mi * 16 + (lane >> 2);
                af[mi][0] = __float_as_uint(A_[m * 20 + kk]);
                af[mi][1] = __float_as_uint(A_[(m + 8) * 20 + kk]);
                af[mi][2] = __float_as_uint(A_[m * 20 + kk + 4]);
                af[mi][3] = __float_as_uint(A_[(m + 8) * 20 + kk + 4]);
            }
            #pragma unroll
            for (int ni = 0; ni < 2; ni++) {
                int n = wn + ni * 8 + (lane >> 2);
                bf[ni][0] = __float_as_uint(B_[kk * 136 + n]);
                bf[ni][1] = __float_as_uint(B_[(kk + 4) * 136 + n]);
            }
            #pragma unroll
            for (int mi = 0; mi < 4; mi++)
                #pragma unroll
                for (int ni = 0; ni < 2; ni++)
                    mma_tf32(acc[mi][ni], af[mi][0], af[mi][1], af[mi][2], af[mi][3],
                             bf[ni][0], bf[ni][1]);
        }
    }

    #pragma unroll
    for (int mi = 0; mi < 4; mi++)
        #pragma unroll
        for (int ni = 0; ni < 2; ni++)
            #pragma unroll
            for (int h = 0; h < 2; h++) {
                int e = mi * 16 + (lane >> 2) + h * 8;
                int n = n0 + wn + ni * 8 + 2 * (lane & 3);
                out[((size_t)b * NN + n) * EE + e]       = acc[mi][ni][2 * h + 0];
                out[((size_t)b * NN + n + 1) * EE + e]   = acc[mi][ni][2 * h + 1];
            }
}

// ---------------- launch ---------------------------------------------------
extern "C" void kernel_launch(void* const* d_in, const int* in_sizes, int n_in,
                              void* d_out, int out_size)
{
    const float* emb = (const float*)d_in[0];
    const float* Wq  = (const float*)d_in[1];
    const float* Wk  = (const float*)d_in[2];
    const float* Wv  = (const float*)d_in[3];
    const float* Wo  = (const float*)d_in[4];
    float* out = (float*)d_out;

    static bool attr_done = false;
    if (!attr_done) {
        cudaFuncSetAttribute(k_scores, cudaFuncAttributeMaxDynamicSharedMemorySize, DSMEM);
        cudaFuncSetAttribute(k_ctx,    cudaFuncAttributeMaxDynamicSharedMemorySize, DSMEM);
        attr_done = true;
    }

    dim3 g1(16, 8, 24);
    k_proj<<<g1, 256>>>(emb, Wq, Wk, Wv);

    dim3 g2(CC / 128, DD / 128, BB);     // 4 x 32 x 8 = 1024 blocks
    k_scores<<<g2, 256, DSMEM>>>();

    dim3 g3(512, 8);
    k_softmax<<<g3, 128>>>();

    dim3 g4(CC / 128, NN / 128, BB);     // 4 x 8 x 8 = 256 blocks
    k_ctx<<<g4, 256, DSMEM>>>();

    dim3 g5(NN / 128, BB);               // 8 x 8
    k_out<<<g5, 256>>>(Wo, out);
}